// round 13
// baseline (speedup 1.0000x reference)
#include <cuda_runtime.h>
#include <cuda_fp16.h>

#define Hdim 256
#define Ddim 512
#define Bdim 256
#define Tdim 64
#define RPB  2
#define NBLK (Bdim / RPB)      // 128 CTAs -> 128 SMs busy
#define THR  512               // 2 k-halves x 256 lanes
#define KP   (Hdim / 2)        // 128 k-pairs total
#define KPH  (KP / 2)          // 64 k-pairs per thread (split-k)
#define NG   (KP / 4)          // 32 GRU 4-kp groups
#define NGH  (NG / 2)          // 16 groups per k-half
#define NGS  16                // groups resident in smem (192 KB) = kh=0's share

#define SM_W_BYTES (NGS * 3 * Hdim * 16)     // 196608
#define SM_H_BYTES (2 * 2 * Hdim * 2)        // 2 bufs x 2 rows x 256 half = 2048
#define SM_X_BYTES (3 * THR * 8)             // gate-exchange float2 x3 (aliases spart)
#define SM_T_BYTES (5 * Tdim * 4)
#define SMEM_BYTES (SM_W_BYTES + SM_H_BYTES + SM_X_BYTES + SM_T_BYTES)

// fp16 k-pair packed weights (layouts unchanged from R11).
__device__ __half2 g_Mh[KP * Hdim];
__device__ float   g_c[Hdim];
__device__ uint4   g_Wp[NG * 3 * Hdim];
__device__ float   g_Macc[8][Hdim][Hdim];   // prep scratch (2 MB)

// Classic RK4
__constant__ float Ccoef[4] = {0.f, 0.5f, 0.5f, 1.f};
__constant__ float Wcoef[4] = {1.f/6.f, 1.f/3.f, 1.f/3.f, 1.f/6.f};

__device__ __forceinline__ float ftanh(float x) {
    float y;
    asm("tanh.approx.f32 %0, %1;" : "=f"(y) : "f"(x));
    return y;
}
__device__ __forceinline__ __half2 u2h2(unsigned u) {
    return *reinterpret_cast<__half2*>(&u);
}
__device__ __forceinline__ void fadd2(float2& a, float2 b) {
    unsigned long long& au = reinterpret_cast<unsigned long long&>(a);
    unsigned long long  bu = reinterpret_cast<unsigned long long&>(b);
    asm("add.rn.f32x2 %0, %0, %1;" : "+l"(au) : "l"(bu));
}

// ---------------------------------------------------------------------------
// prep_M1 / prep_M2 / prep_Wg: unchanged from R11.
// ---------------------------------------------------------------------------
__global__ void prep_M1(const float* __restrict__ W1, const float* __restrict__ W2) {
    const int j0 = blockIdx.x * 4;
    const int c0 = blockIdx.y * 64;
    const int k  = threadIdx.x;
    __shared__ float w2s[4 * 64];
    w2s[k] = W2[(j0 + (k >> 6)) * Ddim + c0 + (k & 63)];
    __syncthreads();
    float a0 = 0.f, a1 = 0.f, a2 = 0.f, a3 = 0.f;
#pragma unroll 8
    for (int dd = 0; dd < 64; dd++) {
        const float w1v = W1[(c0 + dd) * Hdim + k];
        a0 = fmaf(w1v, w2s[0 * 64 + dd], a0);
        a1 = fmaf(w1v, w2s[1 * 64 + dd], a1);
        a2 = fmaf(w1v, w2s[2 * 64 + dd], a2);
        a3 = fmaf(w1v, w2s[3 * 64 + dd], a3);
    }
    g_Macc[blockIdx.y][j0 + 0][k] = a0;
    g_Macc[blockIdx.y][j0 + 1][k] = a1;
    g_Macc[blockIdx.y][j0 + 2][k] = a2;
    g_Macc[blockIdx.y][j0 + 3][k] = a3;
}

__global__ void prep_M2(const float* __restrict__ W2, const float* __restrict__ b1,
                        const float* __restrict__ b2) {
    const int j = blockIdx.x;
    const int k = threadIdx.x;
    float m = 0.f;
#pragma unroll
    for (int c = 0; c < 8; c++) m += g_Macc[c][j][k];
    __half* Mh = (__half*)g_Mh;
    Mh[(k >> 1) * (Hdim * 2) + j * 2 + (k & 1)] = __float2half_rn(m);

    __shared__ float red[Hdim];
    red[k] = W2[j * Ddim + k] * b1[k] + W2[j * Ddim + Hdim + k] * b1[Hdim + k];
    __syncthreads();
    for (int s = 128; s > 0; s >>= 1) {
        if (k < s) red[k] += red[k + s];
        __syncthreads();
    }
    if (k == 0) g_c[j] = red[0] + b2[j];
}

__global__ void prep_Wg(const float* __restrict__ W_hh) {
    const int j  = blockIdx.x;
    const int kp = threadIdx.x;
    const int g  = kp >> 2, q = kp & 3;
    const int k0 = 2 * kp, k1 = 2 * kp + 1;
    float r0 = W_hh[(0 * Hdim + j) * Hdim + k0], r1 = W_hh[(0 * Hdim + j) * Hdim + k1];
    float z0 = W_hh[(1 * Hdim + j) * Hdim + k0], z1 = W_hh[(1 * Hdim + j) * Hdim + k1];
    float n0 = W_hh[(2 * Hdim + j) * Hdim + k0], n1 = W_hh[(2 * Hdim + j) * Hdim + k1];
    __half2 hr = __floats2half2_rn(r0, r1);
    __half2 hz = __floats2half2_rn(z0, z1);
    __half2 hn = __floats2half2_rn(n0, n1);
    unsigned* W = (unsigned*)g_Wp;
    const int s0 = 3 * q;
#pragma unroll
    for (int c = 0; c < 3; c++) {
        const int s = s0 + c;
        unsigned v = (c == 0) ? *reinterpret_cast<unsigned*>(&hr)
                   : (c == 1) ? *reinterpret_cast<unsigned*>(&hz)
                              : *reinterpret_cast<unsigned*>(&hn);
        W[((g * 3 + (s >> 2)) * Hdim + j) * 4 + (s & 3)] = v;
    }
}

// ---------------------------------------------------------------------------
// ODE partial dot over this thread's 64 k-pairs, both rows.
// ---------------------------------------------------------------------------
__device__ __forceinline__ void ode_partial(const float4* __restrict__ h04,
                                            const float4* __restrict__ h14,
                                            const __half2 (&mreg)[KPH],
                                            float& p0, float& p1) {
    float2 a0p = make_float2(0.f, 0.f), a1p = make_float2(0.f, 0.f);
    const __half2 z2 = __floats2half2_rn(0.f, 0.f);
#pragma unroll
    for (int c = 0; c < 2; c++) {           // 2 chunks x 32 kp
        __half2 s0 = z2, s1 = z2;
#pragma unroll
        for (int q = 0; q < 8; q++) {
            float4 v0 = h04[c * 8 + q];
            float4 v1 = h14[c * 8 + q];
            const __half2* pp0 = (const __half2*)&v0;
            const __half2* pp1 = (const __half2*)&v1;
#pragma unroll
            for (int u = 0; u < 4; u++) {
                const __half2 m = mreg[c * 32 + q * 4 + u];
                s0 = __hfma2(m, pp0[u], s0);
                s1 = __hfma2(m, pp1[u], s1);
            }
        }
        fadd2(a0p, __half22float2(s0));
        fadd2(a1p, __half22float2(s1));
    }
    p0 = a0p.x + a0p.y;
    p1 = a1p.x + a1p.y;
}

#define GRU_GROUP(u0, u1, u2, hv0, hv1)                                         \
    do {                                                                        \
        const __half2* p0 = (const __half2*)&hv0;                               \
        const __half2* p1 = (const __half2*)&hv1;                               \
        const __half2 wr0 = u2h2(u0.x), wz0 = u2h2(u0.y), wn0 = u2h2(u0.z);     \
        const __half2 wr1 = u2h2(u0.w), wz1 = u2h2(u1.x), wn1 = u2h2(u1.y);     \
        const __half2 wr2 = u2h2(u1.z), wz2 = u2h2(u1.w), wn2 = u2h2(u2.x);     \
        const __half2 wr3 = u2h2(u2.y), wz3 = u2h2(u2.z), wn3 = u2h2(u2.w);     \
        cr0 = __hfma2(wr0, p0[0], cr0); cr1 = __hfma2(wr0, p1[0], cr1);         \
        cz0 = __hfma2(wz0, p0[0], cz0); cz1 = __hfma2(wz0, p1[0], cz1);         \
        cn0 = __hfma2(wn0, p0[0], cn0); cn1 = __hfma2(wn0, p1[0], cn1);         \
        cr0 = __hfma2(wr1, p0[1], cr0); cr1 = __hfma2(wr1, p1[1], cr1);         \
        cz0 = __hfma2(wz1, p0[1], cz0); cz1 = __hfma2(wz1, p1[1], cz1);         \
        cn0 = __hfma2(wn1, p0[1], cn0); cn1 = __hfma2(wn1, p1[1], cn1);         \
        cr0 = __hfma2(wr2, p0[2], cr0); cr1 = __hfma2(wr2, p1[2], cr1);         \
        cz0 = __hfma2(wz2, p0[2], cz0); cz1 = __hfma2(wz2, p1[2], cz1);         \
        cn0 = __hfma2(wn2, p0[2], cn0); cn1 = __hfma2(wn2, p1[2], cn1);         \
        cr0 = __hfma2(wr3, p0[3], cr0); cr1 = __hfma2(wr3, p1[3], cr1);         \
        cz0 = __hfma2(wz3, p0[3], cz0); cz1 = __hfma2(wz3, p1[3], cz1);         \
        cn0 = __hfma2(wn3, p0[3], cn0); cn1 = __hfma2(wn3, p1[3], cn1);         \
    } while (0)

// ---------------------------------------------------------------------------
// Main recurrent kernel, split-k: 512 threads = 2 k-halves x 256 lanes.
// Thread (kh, j): M[kh-half] column j in 64 half2 regs; owns row kh's state.
// Per f-eval: local partial dot + fp32 smem exchange with partner thread.
// ---------------------------------------------------------------------------
__global__ void __launch_bounds__(THR, 1) rnn_kernel(
    const float* __restrict__ batch, const float* __restrict__ mask,
    const float* __restrict__ W_ih, const float* __restrict__ b_ih,
    const float* __restrict__ b_hh, float* __restrict__ out) {

    extern __shared__ __align__(16) unsigned char smem_raw[];
    uint4*  sWp   = (uint4*)smem_raw;
    __half* hbuf0 = (__half*)(smem_raw + SM_W_BYTES);      // buf0: row0|row1
    __half* hbuf1 = hbuf0 + 2 * Hdim;                      // buf1: row0|row1
    float2* sgr   = (float2*)(smem_raw + SM_W_BYTES + SM_H_BYTES);
    float2* sgz   = sgr + THR;
    float2* sgn   = sgz + THR;
    float2* spart = sgr;                                   // aliases sgr (bar-separated)
    float*  sdt   = (float*)(smem_raw + SM_W_BYTES + SM_H_BYTES + SM_X_BYTES);
    float*  sx0   = sdt + Tdim;
    float*  sx1   = sx0 + Tdim;
    float*  sm0   = sx1 + Tdim;
    float*  sm1   = sm0 + Tdim;

    const int t    = threadIdx.x;
    const int j    = t & (Hdim - 1);
    const int kh   = t >> 8;                 // k-half: 0 or 1
    const int row0 = blockIdx.x * RPB;

    // cooperative copy of the smem-resident W_hh slab (192 KB)
    {
        const float4* s1 = (const float4*)g_Wp;
        float4*       d1 = (float4*)sWp;
        for (int i = t; i < SM_W_BYTES / 16; i += THR) d1[i] = s1[i];
    }
    // per-step scalar tables
    if (t < Tdim) {
        const float t1v = batch[t * 2];
        const float t0v = (t == 0) ? 0.f : batch[(t - 1) * 2];
        sdt[t] = t1v - t0v;
        sx0[t] = batch[((row0    ) * Tdim + t) * 2 + 1];
        sx1[t] = batch[((row0 + 1) * Tdim + t) * 2 + 1];
        sm0[t] = mask[(row0    ) * Tdim + t];
        sm1[t] = mask[(row0 + 1) * Tdim + t];
    }

    // this thread's M half-column -> 64 half2 registers
    __half2 mreg[KPH];
#pragma unroll
    for (int i = 0; i < KPH; i++) mreg[i] = g_Mh[(kh * KPH + i) * Hdim + j];

    const float cj   = g_c[j];
    const float wih0 = W_ih[j], wih1 = W_ih[Hdim + j], wih2 = W_ih[2 * Hdim + j];
    const float bih0 = b_ih[j], bih1 = b_ih[Hdim + j], bih2 = b_ih[2 * Hdim + j];
    const float bhh0 = b_hh[j], bhh1 = b_hh[Hdim + j], bhh2 = b_hh[2 * Hdim + j];

    const float* sxk = kh ? sx1 : sx0;
    const float* smk = kh ? sm1 : sm0;

    __syncthreads();   // slab + tables ready

    float hbr = 0.f;   // row kh's hidden state, lane j
    int pb = 0;        // parity of next smem h write

#pragma unroll 1
    for (int tt = 0; tt < Tdim; tt++) {
        const float dt = sdt[tt];
        const float xv = sxk[tt];
        const float mv = smk[tt];

        // ---- RK4: 4 stages ----
        float kprev = 0.f, acc = 0.f;
#pragma unroll 1
        for (int s = 0; s < 4; s++) {
            const float in = fmaf(Ccoef[s] * dt, kprev, hbr);
            __half* buf = pb ? hbuf1 : hbuf0;
            buf[kh * Hdim + j] = __float2half_rn(in);      // write own row
            __syncthreads();                               // h visible

            float p0, p1;
            ode_partial((const float4*)buf + kh * 16,
                        (const float4*)(buf + Hdim) + kh * 16, mreg, p0, p1);
            spart[t] = make_float2(p0, p1);
            __syncthreads();                               // partials visible
            const float2 q = spart[t ^ 256];
            const float full = kh ? (cj + p1 + q.y) : (cj + p0 + q.x);
            const float o = ftanh(full);
            acc = fmaf(Wcoef[s], o, acc);
            kprev = o;
            pb ^= 1;
        }

        const float hp = fmaf(dt, acc, hbr);               // row kh's ODE output
        __half* buf = pb ? hbuf1 : hbuf0;
        buf[kh * Hdim + j] = __float2half_rn(hp);
        __syncthreads();
        pb ^= 1;

        // ---- GRU partial over this thread's 16 groups ----
        const float4* h0q = (const float4*)buf;
        const float4* h1q = (const float4*)(buf + Hdim);
        float2 gr0p = {0.f, 0.f}, gr1p = {0.f, 0.f};
        float2 gz0p = {0.f, 0.f}, gz1p = {0.f, 0.f};
        float2 gn0p = {0.f, 0.f}, gn1p = {0.f, 0.f};
        const __half2 z2 = __floats2half2_rn(0.f, 0.f);

#pragma unroll
        for (int hblk = 0; hblk < 2; hblk++) {
            __half2 cr0 = z2, cr1 = z2, cz0 = z2, cz1 = z2, cn0 = z2, cn1 = z2;
            if (kh == 0) {                   // groups 0..15 from smem
#pragma unroll
                for (int gg = 0; gg < 8; gg++) {
                    const int g = hblk * 8 + gg;
                    uint4 u0 = sWp[(g * 3 + 0) * Hdim + j];
                    uint4 u1 = sWp[(g * 3 + 1) * Hdim + j];
                    uint4 u2 = sWp[(g * 3 + 2) * Hdim + j];
                    float4 hv0 = h0q[g];
                    float4 hv1 = h1q[g];
                    GRU_GROUP(u0, u1, u2, hv0, hv1);
                }
            } else {                         // groups 16..31 streamed (L2-hot)
#pragma unroll
                for (int gg = 0; gg < 8; gg++) {
                    const int g = NGH + hblk * 8 + gg;
                    uint4 u0 = __ldg(&g_Wp[(g * 3 + 0) * Hdim + j]);
                    uint4 u1 = __ldg(&g_Wp[(g * 3 + 1) * Hdim + j]);
                    uint4 u2 = __ldg(&g_Wp[(g * 3 + 2) * Hdim + j]);
                    float4 hv0 = h0q[g];
                    float4 hv1 = h1q[g];
                    GRU_GROUP(u0, u1, u2, hv0, hv1);
                }
            }
            fadd2(gr0p, __half22float2(cr0)); fadd2(gr1p, __half22float2(cr1));
            fadd2(gz0p, __half22float2(cz0)); fadd2(gz1p, __half22float2(cz1));
            fadd2(gn0p, __half22float2(cn0)); fadd2(gn1p, __half22float2(cn1));
        }

        // exchange gate partials with partner k-half
        sgr[t] = make_float2(gr0p.x + gr0p.y, gr1p.x + gr1p.y);
        sgz[t] = make_float2(gz0p.x + gz0p.y, gz1p.x + gz1p.y);
        sgn[t] = make_float2(gn0p.x + gn0p.y, gn1p.x + gn1p.y);
        __syncthreads();
        const float2 qr = sgr[t ^ 256];
        const float2 qz = sgz[t ^ 256];
        const float2 qn = sgn[t ^ 256];
        const float grF = bhh0 + (kh ? (gr1p.x + gr1p.y + qr.y) : (gr0p.x + gr0p.y + qr.x));
        const float gzF = bhh1 + (kh ? (gz1p.x + gz1p.y + qz.y) : (gz0p.x + gz0p.y + qz.x));
        const float gnF = bhh2 + (kh ? (gn1p.x + gn1p.y + qn.y) : (gn0p.x + gn0p.y + qn.x));

        // gates + mask blend (row kh only)
        {
            const float r  = 1.f / (1.f + __expf(-(fmaf(xv, wih0, bih0) + grF)));
            const float zg = 1.f / (1.f + __expf(-(fmaf(xv, wih1, bih1) + gzF)));
            const float n  = tanhf(fmaf(xv, wih2, bih2) + r * gnF);
            const float ht = (1.f - zg) * n + zg * hp;
            hbr = mv * ht + (1.f - mv) * hp;
        }
    }

    out[(row0 + kh) * Hdim + j] = hbr;
}

// ---------------------------------------------------------------------------
extern "C" void kernel_launch(void* const* d_in, const int* in_sizes, int n_in,
                              void* d_out, int out_size) {
    const float* batch = (const float*)d_in[0];
    const float* mask  = (const float*)d_in[1];
    const float* W1    = (const float*)d_in[2];
    const float* b1    = (const float*)d_in[3];
    const float* W2    = (const float*)d_in[4];
    const float* b2    = (const float*)d_in[5];
    const float* W_ih  = (const float*)d_in[6];
    const float* b_ih  = (const float*)d_in[7];
    const float* W_hh  = (const float*)d_in[8];
    const float* b_hh  = (const float*)d_in[9];

    cudaFuncSetAttribute(rnn_kernel, cudaFuncAttributeMaxDynamicSharedMemorySize,
                         SMEM_BYTES);

    prep_M1<<<dim3(64, 8), Hdim>>>(W1, W2);
    prep_Wg<<<Hdim, KP>>>(W_hh);
    prep_M2<<<Hdim, Hdim>>>(W2, b1, b2);
    rnn_kernel<<<NBLK, THR, SMEM_BYTES>>>(batch, mask, W_ih, b_ih, b_hh,
                                          (float*)d_out);
}

// round 14
// speedup vs baseline: 1.0831x; 1.0831x over previous
#include <cuda_runtime.h>
#include <cuda_fp16.h>

#define Hdim 256
#define Ddim 512
#define Bdim 256
#define Tdim 64
#define RPB  2
#define NBLK (Bdim / RPB)      // 128 CTAs -> 128 SMs busy
#define THR  512               // lane pairs: j = t>>1 (256), p = t&1 (row & k-half)
#define KP   (Hdim / 2)        // 128 k-pairs total
#define KPH  (KP / 2)          // 64 k-pairs per thread
#define NGG  16                // GRU gg-groups (each gg has p=0 and p=1 group)
#define NGGS 8                 // gg-groups resident in smem (192 KB)

#define SM_W_BYTES (NGGS * 3 * Hdim * 2 * 16)   // 196608
#define SM_H_BYTES (2 * 2 * Hdim * 2)           // 2 bufs x 2 rows x 256 half
#define SM_T_BYTES (5 * Tdim * 4)
#define SMEM_BYTES (SM_W_BYTES + SM_H_BYTES + SM_T_BYTES)

// g_Mh[kp*256 + j] = (M[2kp][j], M[2kp+1][j])   (unchanged)
// g_Wp: p-interleaved GRU weights: uint4 index ((gg*3 + i)*Hdim + j)*2 + p,
//   gg = group index within k-half (0..15), p = k-half. Word order within the
//   3 uint4 of a (gg,p,j) triple: r0 z0 n0 r1 | z1 n1 r2 z2 | n2 r3 z3 n3.
__device__ __half2 g_Mh[KP * Hdim];
__device__ float   g_c[Hdim];
__device__ uint4   g_Wp[NGG * 3 * Hdim * 2];
__device__ float   g_Macc[8][Hdim][Hdim];   // prep scratch (2 MB)

__constant__ float Ccoef[4] = {0.f, 0.5f, 0.5f, 1.f};
__constant__ float Wcoef[4] = {1.f/6.f, 1.f/3.f, 1.f/3.f, 1.f/6.f};

__device__ __forceinline__ float ftanh(float x) {
    float y;
    asm("tanh.approx.f32 %0, %1;" : "=f"(y) : "f"(x));
    return y;
}
__device__ __forceinline__ __half2 u2h2(unsigned u) {
    return *reinterpret_cast<__half2*>(&u);
}
__device__ __forceinline__ void fadd2(float2& a, float2 b) {
    unsigned long long& au = reinterpret_cast<unsigned long long&>(a);
    unsigned long long  bu = reinterpret_cast<unsigned long long&>(b);
    asm("add.rn.f32x2 %0, %0, %1;" : "+l"(au) : "l"(bu));
}

// ---------------------------------------------------------------------------
// prep_M1 / prep_M2: unchanged.
// ---------------------------------------------------------------------------
__global__ void prep_M1(const float* __restrict__ W1, const float* __restrict__ W2) {
    const int j0 = blockIdx.x * 4;
    const int c0 = blockIdx.y * 64;
    const int k  = threadIdx.x;
    __shared__ float w2s[4 * 64];
    w2s[k] = W2[(j0 + (k >> 6)) * Ddim + c0 + (k & 63)];
    __syncthreads();
    float a0 = 0.f, a1 = 0.f, a2 = 0.f, a3 = 0.f;
#pragma unroll 8
    for (int dd = 0; dd < 64; dd++) {
        const float w1v = W1[(c0 + dd) * Hdim + k];
        a0 = fmaf(w1v, w2s[0 * 64 + dd], a0);
        a1 = fmaf(w1v, w2s[1 * 64 + dd], a1);
        a2 = fmaf(w1v, w2s[2 * 64 + dd], a2);
        a3 = fmaf(w1v, w2s[3 * 64 + dd], a3);
    }
    g_Macc[blockIdx.y][j0 + 0][k] = a0;
    g_Macc[blockIdx.y][j0 + 1][k] = a1;
    g_Macc[blockIdx.y][j0 + 2][k] = a2;
    g_Macc[blockIdx.y][j0 + 3][k] = a3;
}

__global__ void prep_M2(const float* __restrict__ W2, const float* __restrict__ b1,
                        const float* __restrict__ b2) {
    const int j = blockIdx.x;
    const int k = threadIdx.x;
    float m = 0.f;
#pragma unroll
    for (int c = 0; c < 8; c++) m += g_Macc[c][j][k];
    __half* Mh = (__half*)g_Mh;
    Mh[(k >> 1) * (Hdim * 2) + j * 2 + (k & 1)] = __float2half_rn(m);

    __shared__ float red[Hdim];
    red[k] = W2[j * Ddim + k] * b1[k] + W2[j * Ddim + Hdim + k] * b1[Hdim + k];
    __syncthreads();
    for (int s = 128; s > 0; s >>= 1) {
        if (k < s) red[k] += red[k + s];
        __syncthreads();
    }
    if (k == 0) g_c[j] = red[0] + b2[j];
}

// ---------------------------------------------------------------------------
// prep_Wg: pack W_hh into the p-interleaved uint4 layout.
// grid = j (256), block = kp (128)
// ---------------------------------------------------------------------------
__global__ void prep_Wg(const float* __restrict__ W_hh) {
    const int j  = blockIdx.x;
    const int kp = threadIdx.x;
    const int g  = kp >> 2;          // global group 0..31
    const int q4 = kp & 3;           // kp within group
    const int p  = g >> 4;           // k-half
    const int gg = g & 15;           // group within k-half
    const int k0 = 2 * kp, k1 = 2 * kp + 1;
    float r0 = W_hh[(0 * Hdim + j) * Hdim + k0], r1 = W_hh[(0 * Hdim + j) * Hdim + k1];
    float z0 = W_hh[(1 * Hdim + j) * Hdim + k0], z1 = W_hh[(1 * Hdim + j) * Hdim + k1];
    float n0 = W_hh[(2 * Hdim + j) * Hdim + k0], n1 = W_hh[(2 * Hdim + j) * Hdim + k1];
    __half2 hr = __floats2half2_rn(r0, r1);
    __half2 hz = __floats2half2_rn(z0, z1);
    __half2 hn = __floats2half2_rn(n0, n1);
    unsigned* W = (unsigned*)g_Wp;
    const int s0 = 3 * q4;
#pragma unroll
    for (int c = 0; c < 3; c++) {
        const int s = s0 + c;
        unsigned v = (c == 0) ? *reinterpret_cast<unsigned*>(&hr)
                   : (c == 1) ? *reinterpret_cast<unsigned*>(&hz)
                              : *reinterpret_cast<unsigned*>(&hn);
        W[((((gg * 3 + (s >> 2)) * Hdim + j) * 2) + p) * 4 + (s & 3)] = v;
    }
}

// process one GRU 4-kp group into the six fp16 gate accumulators
#define GRU_GROUP(u0, u1, u2, hv0, hv1)                                         \
    do {                                                                        \
        const __half2* p0 = (const __half2*)&hv0;                               \
        const __half2* p1 = (const __half2*)&hv1;                               \
        const __half2 wr0 = u2h2(u0.x), wz0 = u2h2(u0.y), wn0 = u2h2(u0.z);     \
        const __half2 wr1 = u2h2(u0.w), wz1 = u2h2(u1.x), wn1 = u2h2(u1.y);     \
        const __half2 wr2 = u2h2(u1.z), wz2 = u2h2(u1.w), wn2 = u2h2(u2.x);     \
        const __half2 wr3 = u2h2(u2.y), wz3 = u2h2(u2.z), wn3 = u2h2(u2.w);     \
        cr0 = __hfma2(wr0, p0[0], cr0); cr1 = __hfma2(wr0, p1[0], cr1);         \
        cz0 = __hfma2(wz0, p0[0], cz0); cz1 = __hfma2(wz0, p1[0], cz1);         \
        cn0 = __hfma2(wn0, p0[0], cn0); cn1 = __hfma2(wn0, p1[0], cn1);         \
        cr0 = __hfma2(wr1, p0[1], cr0); cr1 = __hfma2(wr1, p1[1], cr1);         \
        cz0 = __hfma2(wz1, p0[1], cz0); cz1 = __hfma2(wz1, p1[1], cz1);         \
        cn0 = __hfma2(wn1, p0[1], cn0); cn1 = __hfma2(wn1, p1[1], cn1);         \
        cr0 = __hfma2(wr2, p0[2], cr0); cr1 = __hfma2(wr2, p1[2], cr1);         \
        cz0 = __hfma2(wz2, p0[2], cz0); cz1 = __hfma2(wz2, p1[2], cz1);         \
        cn0 = __hfma2(wn2, p0[2], cn0); cn1 = __hfma2(wn2, p1[2], cn1);         \
        cr0 = __hfma2(wr3, p0[3], cr0); cr1 = __hfma2(wr3, p1[3], cr1);         \
        cz0 = __hfma2(wz3, p0[3], cz0); cz1 = __hfma2(wz3, p1[3], cz1);         \
        cn0 = __hfma2(wn3, p0[3], cn0); cn1 = __hfma2(wn3, p1[3], cn1);         \
    } while (0)

// ---------------------------------------------------------------------------
// Main recurrent kernel. 512 threads: lane pair (t, t^1) = (p=0, p=1) shares
// output lane j = t>>1. Thread (j,p) owns row p AND k-half p: computes partial
// dots for BOTH rows over its k-half, exchanges with its in-warp partner via
// shfl.xor (no extra bars), keeps row p. 5 full bars per step (same as R11),
// 4 warps/SMSP for cross-warp overlap between bars.
// h buffers and weights are p-interleaved so a lane pair's two 16B accesses
// share one 128B wavefront window / coalesce into one memory segment.
// ---------------------------------------------------------------------------
__global__ void __launch_bounds__(THR, 1) rnn_kernel(
    const float* __restrict__ batch, const float* __restrict__ mask,
    const float* __restrict__ W_ih, const float* __restrict__ b_ih,
    const float* __restrict__ b_hh, float* __restrict__ out) {

    extern __shared__ __align__(16) unsigned char smem_raw[];
    uint4*  sWp   = (uint4*)smem_raw;
    __half* hbuf0 = (__half*)(smem_raw + SM_W_BYTES);   // buf0: row0(512B)|row1(512B)
    __half* hbuf1 = hbuf0 + 2 * Hdim;                   // buf1
    float*  sdt   = (float*)(smem_raw + SM_W_BYTES + SM_H_BYTES);
    float*  sx0   = sdt + Tdim;
    float*  sx1   = sx0 + Tdim;
    float*  sm0   = sx1 + Tdim;
    float*  sm1   = sm0 + Tdim;

    const int t    = threadIdx.x;
    const int j    = t >> 1;
    const int p    = t & 1;                  // row index AND k-half
    const int row0 = blockIdx.x * RPB;

    // cooperative copy: smem W slab = gg 0..7 (both p) = first 12288 uint4
    {
        const float4* s1 = (const float4*)g_Wp;
        float4*       d1 = (float4*)sWp;
        for (int i = t; i < SM_W_BYTES / 16; i += THR) d1[i] = s1[i];
    }
    if (t < Tdim) {
        const float t1v = batch[t * 2];
        const float t0v = (t == 0) ? 0.f : batch[(t - 1) * 2];
        sdt[t] = t1v - t0v;
        sx0[t] = batch[((row0    ) * Tdim + t) * 2 + 1];
        sx1[t] = batch[((row0 + 1) * Tdim + t) * 2 + 1];
        sm0[t] = mask[(row0    ) * Tdim + t];
        sm1[t] = mask[(row0 + 1) * Tdim + t];
    }

    // this thread's M half-column -> 64 half2 registers
    __half2 mreg[KPH];
#pragma unroll
    for (int i = 0; i < KPH; i++) mreg[i] = g_Mh[(p * KPH + i) * Hdim + j];

    const float cj   = g_c[j];
    const float wih0 = W_ih[j], wih1 = W_ih[Hdim + j], wih2 = W_ih[2 * Hdim + j];
    const float bih0 = b_ih[j], bih1 = b_ih[Hdim + j], bih2 = b_ih[2 * Hdim + j];
    const float bhh0 = b_hh[j], bhh1 = b_hh[Hdim + j], bhh2 = b_hh[2 * Hdim + j];

    const float* sxk = p ? sx1 : sx0;
    const float* smk = p ? sm1 : sm0;

    // h-buffer byte offset for this thread's write (row p, lane j):
    // row array is p-interleaved float4s: slot(2q + half), q=(j&127)>>3, half=j>>7
    const int wslot  = 2 * ((j & 127) >> 3) + (j >> 7);
    const int woff   = p * 512 + wslot * 16 + (j & 7) * 2;   // bytes within buf

    __syncthreads();

    float hbr = 0.f;
    int pb = 0;

#pragma unroll 1
    for (int tt = 0; tt < Tdim; tt++) {
        const float dt = sdt[tt];
        const float xv = sxk[tt];
        const float mv = smk[tt];

        // ---- RK4: 4 stages ----
        float kprev = 0.f, acc = 0.f;
#pragma unroll 1
        for (int s = 0; s < 4; s++) {
            const float in = fmaf(Ccoef[s] * dt, kprev, hbr);
            __half* buf = pb ? hbuf1 : hbuf0;
            *(__half*)((char*)buf + woff) = __float2half_rn(in);
            __syncthreads();

            // partial dot over k-half p, both rows; pair-shared LDS windows
            const float4* b0 = (const float4*)buf;            // row0, 32 slots
            const float4* b1 = (const float4*)(buf + Hdim);   // row1
            float2 a0p = make_float2(0.f, 0.f), a1p = make_float2(0.f, 0.f);
            const __half2 z2h = __floats2half2_rn(0.f, 0.f);
#pragma unroll
            for (int c = 0; c < 2; c++) {        // 2 chunks x 32 kp
                __half2 s0 = z2h, s1 = z2h;
#pragma unroll
                for (int q8 = 0; q8 < 8; q8++) {
                    const int q = c * 8 + q8;
                    float4 v0 = b0[2 * q + p];
                    float4 v1 = b1[2 * q + p];
                    const __half2* pp0 = (const __half2*)&v0;
                    const __half2* pp1 = (const __half2*)&v1;
#pragma unroll
                    for (int u = 0; u < 4; u++) {
                        const __half2 m = mreg[q * 4 + u];
                        s0 = __hfma2(m, pp0[u], s0);
                        s1 = __hfma2(m, pp1[u], s1);
                    }
                }
                fadd2(a0p, __half22float2(s0));
                fadd2(a1p, __half22float2(s1));
            }
            const float pr0 = a0p.x + a0p.y;     // partial, row0
            const float pr1 = a1p.x + a1p.y;     // partial, row1
            const float psend = p ? pr0 : pr1;   // what partner needs
            const float precv = __shfl_xor_sync(0xFFFFFFFFu, psend, 1);
            const float pmine = p ? pr1 : pr0;
            const float o = ftanh(cj + pmine + precv);
            acc = fmaf(Wcoef[s], o, acc);
            kprev = o;
            pb ^= 1;
        }

        const float hp = fmaf(dt, acc, hbr);
        __half* buf = pb ? hbuf1 : hbuf0;
        *(__half*)((char*)buf + woff) = __float2half_rn(hp);
        __syncthreads();
        pb ^= 1;

        // ---- GRU partials over this thread's 16 gg-groups ----
        const float4* b0 = (const float4*)buf;
        const float4* b1 = (const float4*)(buf + Hdim);
        float2 gr0p = {0.f, 0.f}, gr1p = {0.f, 0.f};
        float2 gz0p = {0.f, 0.f}, gz1p = {0.f, 0.f};
        float2 gn0p = {0.f, 0.f}, gn1p = {0.f, 0.f};
        const __half2 z2h = __floats2half2_rn(0.f, 0.f);

#pragma unroll
        for (int hblk = 0; hblk < 2; hblk++) {
            __half2 cr0 = z2h, cr1 = z2h, cz0 = z2h, cz1 = z2h, cn0 = z2h, cn1 = z2h;
#pragma unroll
            for (int g8 = 0; g8 < 8; g8++) {
                const int gg = hblk * 8 + g8;
                uint4 u0, u1, u2;
                if (hblk == 0) {                 // gg 0..7 from smem (pair-shared)
                    u0 = sWp[((gg * 3 + 0) * Hdim + j) * 2 + p];
                    u1 = sWp[((gg * 3 + 1) * Hdim + j) * 2 + p];
                    u2 = sWp[((gg * 3 + 2) * Hdim + j) * 2 + p];
                } else {                         // gg 8..15 streamed (L2-hot, coalesced)
                    u0 = __ldg(&g_Wp[((gg * 3 + 0) * Hdim + j) * 2 + p]);
                    u1 = __ldg(&g_Wp[((gg * 3 + 1) * Hdim + j) * 2 + p]);
                    u2 = __ldg(&g_Wp[((gg * 3 + 2) * Hdim + j) * 2 + p]);
                }
                float4 hv0 = b0[2 * gg + p];
                float4 hv1 = b1[2 * gg + p];
                GRU_GROUP(u0, u1, u2, hv0, hv1);
            }
            fadd2(gr0p, __half22float2(cr0)); fadd2(gr1p, __half22float2(cr1));
            fadd2(gz0p, __half22float2(cz0)); fadd2(gz1p, __half22float2(cz1));
            fadd2(gn0p, __half22float2(cn0)); fadd2(gn1p, __half22float2(cn1));
        }

        // pairwise gate exchange via shfl (row p kept)
        const float r0s = gr0p.x + gr0p.y, r1s = gr1p.x + gr1p.y;
        const float z0s = gz0p.x + gz0p.y, z1s = gz1p.x + gz1p.y;
        const float n0s = gn0p.x + gn0p.y, n1s = gn1p.x + gn1p.y;
        const float grF = bhh0 + (p ? r1s : r0s)
                        + __shfl_xor_sync(0xFFFFFFFFu, p ? r0s : r1s, 1);
        const float gzF = bhh1 + (p ? z1s : z0s)
                        + __shfl_xor_sync(0xFFFFFFFFu, p ? z0s : z1s, 1);
        const float gnF = bhh2 + (p ? n1s : n0s)
                        + __shfl_xor_sync(0xFFFFFFFFu, p ? n0s : n1s, 1);

        // gates + mask blend (row p): r,n via MUFU tanh; z keeps accurate exp
        {
            const float r  = 0.5f * ftanh(0.5f * (fmaf(xv, wih0, bih0) + grF)) + 0.5f;
            const float zg = 1.f / (1.f + __expf(-(fmaf(xv, wih1, bih1) + gzF)));
            const float n  = ftanh(fmaf(xv, wih2, bih2) + r * gnF);
            const float ht = (1.f - zg) * n + zg * hp;
            hbr = mv * ht + (1.f - mv) * hp;
        }
    }

    out[(row0 + p) * Hdim + j] = hbr;
}

// ---------------------------------------------------------------------------
extern "C" void kernel_launch(void* const* d_in, const int* in_sizes, int n_in,
                              void* d_out, int out_size) {
    const float* batch = (const float*)d_in[0];
    const float* mask  = (const float*)d_in[1];
    const float* W1    = (const float*)d_in[2];
    const float* b1    = (const float*)d_in[3];
    const float* W2    = (const float*)d_in[4];
    const float* b2    = (const float*)d_in[5];
    const float* W_ih  = (const float*)d_in[6];
    const float* b_ih  = (const float*)d_in[7];
    const float* W_hh  = (const float*)d_in[8];
    const float* b_hh  = (const float*)d_in[9];

    cudaFuncSetAttribute(rnn_kernel, cudaFuncAttributeMaxDynamicSharedMemorySize,
                         SMEM_BYTES);

    prep_M1<<<dim3(64, 8), Hdim>>>(W1, W2);
    prep_Wg<<<Hdim, KP>>>(W_hh);
    prep_M2<<<Hdim, Hdim>>>(W2, b1, b2);
    rnn_kernel<<<NBLK, THR, SMEM_BYTES>>>(batch, mask, W_ih, b_ih, b_hh,
                                          (float*)d_out);
}

// round 15
// speedup vs baseline: 1.1309x; 1.0441x over previous
#include <cuda_runtime.h>
#include <cuda_fp16.h>

#define Hdim 256
#define Ddim 512
#define Bdim 256
#define Tdim 64
#define RPB  2
#define NBLK (Bdim / RPB)      // 128 CTAs -> 128 SMs busy
#define THR  512               // lane pairs: j = t>>1 (256), p = t&1 (row & k-half)
#define KP   (Hdim / 2)        // 128 k-pairs total
#define KPH  (KP / 2)          // 64 k-pairs per thread
#define NGG  16                // GRU gg-groups (each gg has p=0 and p=1 group)
#define NGGS 9                 // gg-groups resident in smem (216 KB)

#define SM_W_BYTES (NGGS * 3 * Hdim * 2 * 16)   // 221184
#define SM_H_BYTES (2 * 2 * Hdim * 2)           // 2 bufs x 2 rows x 256 half
#define SM_T_BYTES (5 * Tdim * 4)
#define SMEM_BYTES (SM_W_BYTES + SM_H_BYTES + SM_T_BYTES)

// g_Mh[kp*256 + j] = (M[2kp][j], M[2kp+1][j])
// g_Wp: p-interleaved GRU weights: uint4 index ((gg*3 + i)*Hdim + j)*2 + p,
//   gg = group index within k-half (0..15), p = k-half. Word order within the
//   3 uint4 of a (gg,p,j) triple: r0 z0 n0 r1 | z1 n1 r2 z2 | n2 r3 z3 n3.
__device__ __half2 g_Mh[KP * Hdim];
__device__ float   g_c[Hdim];
__device__ uint4   g_Wp[NGG * 3 * Hdim * 2];
__device__ float   g_Macc[8][Hdim][Hdim];   // prep scratch (2 MB)

__constant__ float Ccoef[4] = {0.f, 0.5f, 0.5f, 1.f};
__constant__ float Wcoef[4] = {1.f/6.f, 1.f/3.f, 1.f/3.f, 1.f/6.f};

__device__ __forceinline__ float ftanh(float x) {
    float y;
    asm("tanh.approx.f32 %0, %1;" : "=f"(y) : "f"(x));
    return y;
}
__device__ __forceinline__ __half2 u2h2(unsigned u) {
    return *reinterpret_cast<__half2*>(&u);
}
__device__ __forceinline__ void fadd2(float2& a, float2 b) {
    unsigned long long& au = reinterpret_cast<unsigned long long&>(a);
    unsigned long long  bu = reinterpret_cast<unsigned long long&>(b);
    asm("add.rn.f32x2 %0, %0, %1;" : "+l"(au) : "l"(bu));
}

// ---------------------------------------------------------------------------
// prep_M1 / prep_M2: unchanged.
// ---------------------------------------------------------------------------
__global__ void prep_M1(const float* __restrict__ W1, const float* __restrict__ W2) {
    const int j0 = blockIdx.x * 4;
    const int c0 = blockIdx.y * 64;
    const int k  = threadIdx.x;
    __shared__ float w2s[4 * 64];
    w2s[k] = W2[(j0 + (k >> 6)) * Ddim + c0 + (k & 63)];
    __syncthreads();
    float a0 = 0.f, a1 = 0.f, a2 = 0.f, a3 = 0.f;
#pragma unroll 8
    for (int dd = 0; dd < 64; dd++) {
        const float w1v = W1[(c0 + dd) * Hdim + k];
        a0 = fmaf(w1v, w2s[0 * 64 + dd], a0);
        a1 = fmaf(w1v, w2s[1 * 64 + dd], a1);
        a2 = fmaf(w1v, w2s[2 * 64 + dd], a2);
        a3 = fmaf(w1v, w2s[3 * 64 + dd], a3);
    }
    g_Macc[blockIdx.y][j0 + 0][k] = a0;
    g_Macc[blockIdx.y][j0 + 1][k] = a1;
    g_Macc[blockIdx.y][j0 + 2][k] = a2;
    g_Macc[blockIdx.y][j0 + 3][k] = a3;
}

__global__ void prep_M2(const float* __restrict__ W2, const float* __restrict__ b1,
                        const float* __restrict__ b2) {
    const int j = blockIdx.x;
    const int k = threadIdx.x;
    float m = 0.f;
#pragma unroll
    for (int c = 0; c < 8; c++) m += g_Macc[c][j][k];
    __half* Mh = (__half*)g_Mh;
    Mh[(k >> 1) * (Hdim * 2) + j * 2 + (k & 1)] = __float2half_rn(m);

    __shared__ float red[Hdim];
    red[k] = W2[j * Ddim + k] * b1[k] + W2[j * Ddim + Hdim + k] * b1[Hdim + k];
    __syncthreads();
    for (int s = 128; s > 0; s >>= 1) {
        if (k < s) red[k] += red[k + s];
        __syncthreads();
    }
    if (k == 0) g_c[j] = red[0] + b2[j];
}

// ---------------------------------------------------------------------------
// prep_Wg: pack W_hh into the p-interleaved uint4 layout. (unchanged)
// ---------------------------------------------------------------------------
__global__ void prep_Wg(const float* __restrict__ W_hh) {
    const int j  = blockIdx.x;
    const int kp = threadIdx.x;
    const int g  = kp >> 2;
    const int q4 = kp & 3;
    const int p  = g >> 4;
    const int gg = g & 15;
    const int k0 = 2 * kp, k1 = 2 * kp + 1;
    float r0 = W_hh[(0 * Hdim + j) * Hdim + k0], r1 = W_hh[(0 * Hdim + j) * Hdim + k1];
    float z0 = W_hh[(1 * Hdim + j) * Hdim + k0], z1 = W_hh[(1 * Hdim + j) * Hdim + k1];
    float n0 = W_hh[(2 * Hdim + j) * Hdim + k0], n1 = W_hh[(2 * Hdim + j) * Hdim + k1];
    __half2 hr = __floats2half2_rn(r0, r1);
    __half2 hz = __floats2half2_rn(z0, z1);
    __half2 hn = __floats2half2_rn(n0, n1);
    unsigned* W = (unsigned*)g_Wp;
    const int s0 = 3 * q4;
#pragma unroll
    for (int c = 0; c < 3; c++) {
        const int s = s0 + c;
        unsigned v = (c == 0) ? *reinterpret_cast<unsigned*>(&hr)
                   : (c == 1) ? *reinterpret_cast<unsigned*>(&hz)
                              : *reinterpret_cast<unsigned*>(&hn);
        W[((((gg * 3 + (s >> 2)) * Hdim + j) * 2) + p) * 4 + (s & 3)] = v;
    }
}

// process one GRU 4-kp group into the six fp16 gate accumulators
#define GRU_GROUP(u0, u1, u2, hv0, hv1)                                         \
    do {                                                                        \
        const __half2* p0 = (const __half2*)&hv0;                               \
        const __half2* p1 = (const __half2*)&hv1;                               \
        const __half2 wr0 = u2h2(u0.x), wz0 = u2h2(u0.y), wn0 = u2h2(u0.z);     \
        const __half2 wr1 = u2h2(u0.w), wz1 = u2h2(u1.x), wn1 = u2h2(u1.y);     \
        const __half2 wr2 = u2h2(u1.z), wz2 = u2h2(u1.w), wn2 = u2h2(u2.x);     \
        const __half2 wr3 = u2h2(u2.y), wz3 = u2h2(u2.z), wn3 = u2h2(u2.w);     \
        cr0 = __hfma2(wr0, p0[0], cr0); cr1 = __hfma2(wr0, p1[0], cr1);         \
        cz0 = __hfma2(wz0, p0[0], cz0); cz1 = __hfma2(wz0, p1[0], cz1);         \
        cn0 = __hfma2(wn0, p0[0], cn0); cn1 = __hfma2(wn0, p1[0], cn1);         \
        cr0 = __hfma2(wr1, p0[1], cr0); cr1 = __hfma2(wr1, p1[1], cr1);         \
        cz0 = __hfma2(wz1, p0[1], cz0); cz1 = __hfma2(wz1, p1[1], cz1);         \
        cn0 = __hfma2(wn1, p0[1], cn0); cn1 = __hfma2(wn1, p1[1], cn1);         \
        cr0 = __hfma2(wr2, p0[2], cr0); cr1 = __hfma2(wr2, p1[2], cr1);         \
        cz0 = __hfma2(wz2, p0[2], cz0); cz1 = __hfma2(wz2, p1[2], cz1);         \
        cn0 = __hfma2(wn2, p0[2], cn0); cn1 = __hfma2(wn2, p1[2], cn1);         \
        cr0 = __hfma2(wr3, p0[3], cr0); cr1 = __hfma2(wr3, p1[3], cr1);         \
        cz0 = __hfma2(wz3, p0[3], cz0); cz1 = __hfma2(wz3, p1[3], cz1);         \
        cn0 = __hfma2(wn3, p0[3], cn0); cn1 = __hfma2(wn3, p1[3], cn1);         \
    } while (0)

// ---------------------------------------------------------------------------
// Main recurrent kernel: R13 structure (lane-pair split-k, shfl exchange,
// 5 bars/step). Changes: paired fp16 accumulators merged via HADD2 (single
// flush), 9 smem / 7 streamed GRU weight groups.
// ---------------------------------------------------------------------------
__global__ void __launch_bounds__(THR, 1) rnn_kernel(
    const float* __restrict__ batch, const float* __restrict__ mask,
    const float* __restrict__ W_ih, const float* __restrict__ b_ih,
    const float* __restrict__ b_hh, float* __restrict__ out) {

    extern __shared__ __align__(16) unsigned char smem_raw[];
    uint4*  sWp   = (uint4*)smem_raw;
    __half* hbuf0 = (__half*)(smem_raw + SM_W_BYTES);   // buf0: row0(512B)|row1(512B)
    __half* hbuf1 = hbuf0 + 2 * Hdim;                   // buf1
    float*  sdt   = (float*)(smem_raw + SM_W_BYTES + SM_H_BYTES);
    float*  sx0   = sdt + Tdim;
    float*  sx1   = sx0 + Tdim;
    float*  sm0   = sx1 + Tdim;
    float*  sm1   = sm0 + Tdim;

    const int t    = threadIdx.x;
    const int j    = t >> 1;
    const int p    = t & 1;                  // row index AND k-half
    const int row0 = blockIdx.x * RPB;

    // cooperative copy: smem W slab = gg 0..8 (both p)
    {
        const float4* s1 = (const float4*)g_Wp;
        float4*       d1 = (float4*)sWp;
        for (int i = t; i < SM_W_BYTES / 16; i += THR) d1[i] = s1[i];
    }
    if (t < Tdim) {
        const float t1v = batch[t * 2];
        const float t0v = (t == 0) ? 0.f : batch[(t - 1) * 2];
        sdt[t] = t1v - t0v;
        sx0[t] = batch[((row0    ) * Tdim + t) * 2 + 1];
        sx1[t] = batch[((row0 + 1) * Tdim + t) * 2 + 1];
        sm0[t] = mask[(row0    ) * Tdim + t];
        sm1[t] = mask[(row0 + 1) * Tdim + t];
    }

    // this thread's M half-column -> 64 half2 registers
    __half2 mreg[KPH];
#pragma unroll
    for (int i = 0; i < KPH; i++) mreg[i] = g_Mh[(p * KPH + i) * Hdim + j];

    const float cj   = g_c[j];
    const float wih0 = W_ih[j], wih1 = W_ih[Hdim + j], wih2 = W_ih[2 * Hdim + j];
    const float bih0 = b_ih[j], bih1 = b_ih[Hdim + j], bih2 = b_ih[2 * Hdim + j];
    const float bhh0 = b_hh[j], bhh1 = b_hh[Hdim + j], bhh2 = b_hh[2 * Hdim + j];

    const float* sxk = p ? sx1 : sx0;
    const float* smk = p ? sm1 : sm0;

    // h-buffer byte offset for this thread's write (row p, lane j):
    // row array is p-interleaved float4s: slot(2q + half), q=(j&127)>>3, half=j>>7
    const int wslot  = 2 * ((j & 127) >> 3) + (j >> 7);
    const int woff   = p * 512 + wslot * 16 + (j & 7) * 2;   // bytes within buf

    __syncthreads();

    float hbr = 0.f;
    int pb = 0;

#pragma unroll 1
    for (int tt = 0; tt < Tdim; tt++) {
        const float dt = sdt[tt];
        const float xv = sxk[tt];
        const float mv = smk[tt];

        // ---- RK4: 4 stages ----
        float kprev = 0.f, acc = 0.f;
#pragma unroll 1
        for (int s = 0; s < 4; s++) {
            const float in = fmaf(Ccoef[s] * dt, kprev, hbr);
            __half* buf = pb ? hbuf1 : hbuf0;
            *(__half*)((char*)buf + woff) = __float2half_rn(in);
            __syncthreads();

            // partial dot over k-half p, both rows; paired accumulators
            // (chains of 32) merged with HADD2 -> single fp32 flush.
            const float4* b0 = (const float4*)buf;            // row0, 32 slots
            const float4* b1 = (const float4*)(buf + Hdim);   // row1
            const __half2 z2h = __floats2half2_rn(0.f, 0.f);
            __half2 sA0 = z2h, sA1 = z2h, sB0 = z2h, sB1 = z2h;
#pragma unroll
            for (int q = 0; q < 8; q++) {        // first 32 kp -> set A
                float4 v0 = b0[2 * q + p];
                float4 v1 = b1[2 * q + p];
                const __half2* pp0 = (const __half2*)&v0;
                const __half2* pp1 = (const __half2*)&v1;
#pragma unroll
                for (int u = 0; u < 4; u++) {
                    const __half2 m = mreg[q * 4 + u];
                    sA0 = __hfma2(m, pp0[u], sA0);
                    sA1 = __hfma2(m, pp1[u], sA1);
                }
            }
#pragma unroll
            for (int q = 8; q < 16; q++) {       // last 32 kp -> set B
                float4 v0 = b0[2 * q + p];
                float4 v1 = b1[2 * q + p];
                const __half2* pp0 = (const __half2*)&v0;
                const __half2* pp1 = (const __half2*)&v1;
#pragma unroll
                for (int u = 0; u < 4; u++) {
                    const __half2 m = mreg[q * 4 + u];
                    sB0 = __hfma2(m, pp0[u], sB0);
                    sB1 = __hfma2(m, pp1[u], sB1);
                }
            }
            const float2 f0 = __half22float2(__hadd2(sA0, sB0));
            const float2 f1 = __half22float2(__hadd2(sA1, sB1));
            const float pr0 = f0.x + f0.y;       // partial, row0
            const float pr1 = f1.x + f1.y;       // partial, row1
            const float psend = p ? pr0 : pr1;
            const float precv = __shfl_xor_sync(0xFFFFFFFFu, psend, 1);
            const float pmine = p ? pr1 : pr0;
            const float o = ftanh(cj + pmine + precv);
            acc = fmaf(Wcoef[s], o, acc);
            kprev = o;
            pb ^= 1;
        }

        const float hp = fmaf(dt, acc, hbr);
        __half* buf = pb ? hbuf1 : hbuf0;
        *(__half*)((char*)buf + woff) = __float2half_rn(hp);
        __syncthreads();
        pb ^= 1;

        // ---- GRU partials: set A = 9 smem groups, set B = 7 streamed ----
        const float4* b0 = (const float4*)buf;
        const float4* b1 = (const float4*)(buf + Hdim);
        const __half2 z2h = __floats2half2_rn(0.f, 0.f);
        __half2 Ar0, Ar1, Az0, Az1, An0, An1;    // set A results
        {
            __half2 cr0 = z2h, cr1 = z2h, cz0 = z2h, cz1 = z2h, cn0 = z2h, cn1 = z2h;
#pragma unroll
            for (int gg = 0; gg < NGGS; gg++) {  // smem-resident (pair-shared)
                uint4 u0 = sWp[((gg * 3 + 0) * Hdim + j) * 2 + p];
                uint4 u1 = sWp[((gg * 3 + 1) * Hdim + j) * 2 + p];
                uint4 u2 = sWp[((gg * 3 + 2) * Hdim + j) * 2 + p];
                float4 hv0 = b0[2 * gg + p];
                float4 hv1 = b1[2 * gg + p];
                GRU_GROUP(u0, u1, u2, hv0, hv1);
            }
            Ar0 = cr0; Ar1 = cr1; Az0 = cz0; Az1 = cz1; An0 = cn0; An1 = cn1;
        }
        {
            __half2 cr0 = z2h, cr1 = z2h, cz0 = z2h, cz1 = z2h, cn0 = z2h, cn1 = z2h;
#pragma unroll
            for (int gg = NGGS; gg < NGG; gg++) {   // L2-streamed, coalesced
                uint4 u0 = __ldg(&g_Wp[((gg * 3 + 0) * Hdim + j) * 2 + p]);
                uint4 u1 = __ldg(&g_Wp[((gg * 3 + 1) * Hdim + j) * 2 + p]);
                uint4 u2 = __ldg(&g_Wp[((gg * 3 + 2) * Hdim + j) * 2 + p]);
                float4 hv0 = b0[2 * gg + p];
                float4 hv1 = b1[2 * gg + p];
                GRU_GROUP(u0, u1, u2, hv0, hv1);
            }
            Ar0 = __hadd2(Ar0, cr0); Ar1 = __hadd2(Ar1, cr1);
            Az0 = __hadd2(Az0, cz0); Az1 = __hadd2(Az1, cz1);
            An0 = __hadd2(An0, cn0); An1 = __hadd2(An1, cn1);
        }

        const float2 fr0 = __half22float2(Ar0), fr1 = __half22float2(Ar1);
        const float2 fz0 = __half22float2(Az0), fz1 = __half22float2(Az1);
        const float2 fn0 = __half22float2(An0), fn1 = __half22float2(An1);
        const float r0s = fr0.x + fr0.y, r1s = fr1.x + fr1.y;
        const float z0s = fz0.x + fz0.y, z1s = fz1.x + fz1.y;
        const float n0s = fn0.x + fn0.y, n1s = fn1.x + fn1.y;

        // pairwise gate exchange via shfl (row p kept)
        const float grF = bhh0 + (p ? r1s : r0s)
                        + __shfl_xor_sync(0xFFFFFFFFu, p ? r0s : r1s, 1);
        const float gzF = bhh1 + (p ? z1s : z0s)
                        + __shfl_xor_sync(0xFFFFFFFFu, p ? z0s : z1s, 1);
        const float gnF = bhh2 + (p ? n1s : n0s)
                        + __shfl_xor_sync(0xFFFFFFFFu, p ? n0s : n1s, 1);

        // gates + mask blend (row p): r,n via MUFU tanh; z keeps accurate exp
        {
            const float r  = 0.5f * ftanh(0.5f * (fmaf(xv, wih0, bih0) + grF)) + 0.5f;
            const float zg = 1.f / (1.f + __expf(-(fmaf(xv, wih1, bih1) + gzF)));
            const float n  = ftanh(fmaf(xv, wih2, bih2) + r * gnF);
            const float ht = (1.f - zg) * n + zg * hp;
            hbr = mv * ht + (1.f - mv) * hp;
        }
    }

    out[(row0 + p) * Hdim + j] = hbr;
}

// ---------------------------------------------------------------------------
extern "C" void kernel_launch(void* const* d_in, const int* in_sizes, int n_in,
                              void* d_out, int out_size) {
    const float* batch = (const float*)d_in[0];
    const float* mask  = (const float*)d_in[1];
    const float* W1    = (const float*)d_in[2];
    const float* b1    = (const float*)d_in[3];
    const float* W2    = (const float*)d_in[4];
    const float* b2    = (const float*)d_in[5];
    const float* W_ih  = (const float*)d_in[6];
    const float* b_ih  = (const float*)d_in[7];
    const float* W_hh  = (const float*)d_in[8];
    const float* b_hh  = (const float*)d_in[9];

    cudaFuncSetAttribute(rnn_kernel, cudaFuncAttributeMaxDynamicSharedMemorySize,
                         SMEM_BYTES);

    prep_M1<<<dim3(64, 8), Hdim>>>(W1, W2);
    prep_Wg<<<Hdim, KP>>>(W_hh);
    prep_M2<<<Hdim, Hdim>>>(W2, b1, b2);
    rnn_kernel<<<NBLK, THR, SMEM_BYTES>>>(batch, mask, W_ih, b_ih, b_hh,
                                          (float*)d_out);
}

// round 16
// speedup vs baseline: 1.1483x; 1.0153x over previous
#include <cuda_runtime.h>
#include <cuda_fp16.h>

#define Hdim 256
#define Ddim 512
#define Bdim 256
#define Tdim 64
#define RPB  2
#define NBLK (Bdim / RPB)      // 128 CTAs -> 128 SMs busy
#define THR  512               // lane pairs: j = t>>1 (256), p = t&1 (row & k-half)
#define KP   (Hdim / 2)        // 128 k-pairs total
#define KPH  (KP / 2)          // 64 k-pairs per thread
#define NGG  16                // GRU gg-groups (each gg has p=0 and p=1 group)
#define NGGS 9                 // gg-groups resident in smem (216 KB)
#define NGST (NGG - NGGS)      // 7 streamed groups

#define SM_W_BYTES (NGGS * 3 * Hdim * 2 * 16)   // 221184
#define SM_H_BYTES (2 * 2 * Hdim * 2)           // 2 bufs x 2 rows x 256 half
#define SM_T_BYTES (5 * Tdim * 4)
#define SMEM_BYTES (SM_W_BYTES + SM_H_BYTES + SM_T_BYTES)

// g_Mh[kp*256 + j] = (M[2kp][j], M[2kp+1][j])
// g_Wp: p-interleaved GRU weights: uint4 index ((gg*3 + i)*Hdim + j)*2 + p.
// Word order in the 3 uint4 of a (gg,p,j) triple:
//   r0 z0 n0 r1 | z1 n1 r2 z2 | n2 r3 z3 n3.
__device__ __half2 g_Mh[KP * Hdim];
__device__ float   g_c[Hdim];
__device__ uint4   g_Wp[NGG * 3 * Hdim * 2];
__device__ float   g_Macc[8][Hdim][Hdim];   // prep scratch (2 MB)

__constant__ float Ccoef[4] = {0.f, 0.5f, 0.5f, 1.f};
__constant__ float Wcoef[4] = {1.f/6.f, 1.f/3.f, 1.f/3.f, 1.f/6.f};

__device__ __forceinline__ float ftanh(float x) {
    float y;
    asm("tanh.approx.f32 %0, %1;" : "=f"(y) : "f"(x));
    return y;
}
__device__ __forceinline__ __half2 u2h2(unsigned u) {
    return *reinterpret_cast<__half2*>(&u);
}

// ---------------------------------------------------------------------------
// prep_M1 / prep_M2 / prep_Wg: unchanged.
// ---------------------------------------------------------------------------
__global__ void prep_M1(const float* __restrict__ W1, const float* __restrict__ W2) {
    const int j0 = blockIdx.x * 4;
    const int c0 = blockIdx.y * 64;
    const int k  = threadIdx.x;
    __shared__ float w2s[4 * 64];
    w2s[k] = W2[(j0 + (k >> 6)) * Ddim + c0 + (k & 63)];
    __syncthreads();
    float a0 = 0.f, a1 = 0.f, a2 = 0.f, a3 = 0.f;
#pragma unroll 8
    for (int dd = 0; dd < 64; dd++) {
        const float w1v = W1[(c0 + dd) * Hdim + k];
        a0 = fmaf(w1v, w2s[0 * 64 + dd], a0);
        a1 = fmaf(w1v, w2s[1 * 64 + dd], a1);
        a2 = fmaf(w1v, w2s[2 * 64 + dd], a2);
        a3 = fmaf(w1v, w2s[3 * 64 + dd], a3);
    }
    g_Macc[blockIdx.y][j0 + 0][k] = a0;
    g_Macc[blockIdx.y][j0 + 1][k] = a1;
    g_Macc[blockIdx.y][j0 + 2][k] = a2;
    g_Macc[blockIdx.y][j0 + 3][k] = a3;
}

__global__ void prep_M2(const float* __restrict__ W2, const float* __restrict__ b1,
                        const float* __restrict__ b2) {
    const int j = blockIdx.x;
    const int k = threadIdx.x;
    float m = 0.f;
#pragma unroll
    for (int c = 0; c < 8; c++) m += g_Macc[c][j][k];
    __half* Mh = (__half*)g_Mh;
    Mh[(k >> 1) * (Hdim * 2) + j * 2 + (k & 1)] = __float2half_rn(m);

    __shared__ float red[Hdim];
    red[k] = W2[j * Ddim + k] * b1[k] + W2[j * Ddim + Hdim + k] * b1[Hdim + k];
    __syncthreads();
    for (int s = 128; s > 0; s >>= 1) {
        if (k < s) red[k] += red[k + s];
        __syncthreads();
    }
    if (k == 0) g_c[j] = red[0] + b2[j];
}

__global__ void prep_Wg(const float* __restrict__ W_hh) {
    const int j  = blockIdx.x;
    const int kp = threadIdx.x;
    const int g  = kp >> 2;
    const int q4 = kp & 3;
    const int p  = g >> 4;
    const int gg = g & 15;
    const int k0 = 2 * kp, k1 = 2 * kp + 1;
    float r0 = W_hh[(0 * Hdim + j) * Hdim + k0], r1 = W_hh[(0 * Hdim + j) * Hdim + k1];
    float z0 = W_hh[(1 * Hdim + j) * Hdim + k0], z1 = W_hh[(1 * Hdim + j) * Hdim + k1];
    float n0 = W_hh[(2 * Hdim + j) * Hdim + k0], n1 = W_hh[(2 * Hdim + j) * Hdim + k1];
    __half2 hr = __floats2half2_rn(r0, r1);
    __half2 hz = __floats2half2_rn(z0, z1);
    __half2 hn = __floats2half2_rn(n0, n1);
    unsigned* W = (unsigned*)g_Wp;
    const int s0 = 3 * q4;
#pragma unroll
    for (int c = 0; c < 3; c++) {
        const int s = s0 + c;
        unsigned v = (c == 0) ? *reinterpret_cast<unsigned*>(&hr)
                   : (c == 1) ? *reinterpret_cast<unsigned*>(&hz)
                              : *reinterpret_cast<unsigned*>(&hn);
        W[((((gg * 3 + (s >> 2)) * Hdim + j) * 2) + p) * 4 + (s & 3)] = v;
    }
}

// process one GRU 4-kp group into six named fp16 gate accumulators
#define GRU_GROUP6(cr0, cr1, cz0, cz1, cn0, cn1, u0, u1, u2, hv0, hv1)          \
    do {                                                                        \
        const __half2* p0 = (const __half2*)&hv0;                               \
        const __half2* p1 = (const __half2*)&hv1;                               \
        const __half2 wr0 = u2h2(u0.x), wz0 = u2h2(u0.y), wn0 = u2h2(u0.z);     \
        const __half2 wr1 = u2h2(u0.w), wz1 = u2h2(u1.x), wn1 = u2h2(u1.y);     \
        const __half2 wr2 = u2h2(u1.z), wz2 = u2h2(u1.w), wn2 = u2h2(u2.x);     \
        const __half2 wr3 = u2h2(u2.y), wz3 = u2h2(u2.z), wn3 = u2h2(u2.w);     \
        cr0 = __hfma2(wr0, p0[0], cr0); cr1 = __hfma2(wr0, p1[0], cr1);         \
        cz0 = __hfma2(wz0, p0[0], cz0); cz1 = __hfma2(wz0, p1[0], cz1);         \
        cn0 = __hfma2(wn0, p0[0], cn0); cn1 = __hfma2(wn0, p1[0], cn1);         \
        cr0 = __hfma2(wr1, p0[1], cr0); cr1 = __hfma2(wr1, p1[1], cr1);         \
        cz0 = __hfma2(wz1, p0[1], cz0); cz1 = __hfma2(wz1, p1[1], cz1);         \
        cn0 = __hfma2(wn1, p0[1], cn0); cn1 = __hfma2(wn1, p1[1], cn1);         \
        cr0 = __hfma2(wr2, p0[2], cr0); cr1 = __hfma2(wr2, p1[2], cr1);         \
        cz0 = __hfma2(wz2, p0[2], cz0); cz1 = __hfma2(wz2, p1[2], cz1);         \
        cn0 = __hfma2(wn2, p0[2], cn0); cn1 = __hfma2(wn2, p1[2], cn1);         \
        cr0 = __hfma2(wr3, p0[3], cr0); cr1 = __hfma2(wr3, p1[3], cr1);         \
        cz0 = __hfma2(wz3, p0[3], cz0); cz1 = __hfma2(wz3, p1[3], cz1);         \
        cn0 = __hfma2(wn3, p0[3], cn0); cn1 = __hfma2(wn3, p1[3], cn1);         \
    } while (0)

// ---------------------------------------------------------------------------
// Main recurrent kernel: R14 structure + depth-2 pipelined streamed GRU
// weights, CTA-uniform GRU skip, all-tanh gates.
// ---------------------------------------------------------------------------
__global__ void __launch_bounds__(THR, 1) rnn_kernel(
    const float* __restrict__ batch, const float* __restrict__ mask,
    const float* __restrict__ W_ih, const float* __restrict__ b_ih,
    const float* __restrict__ b_hh, float* __restrict__ out) {

    extern __shared__ __align__(16) unsigned char smem_raw[];
    uint4*  sWp   = (uint4*)smem_raw;
    __half* hbuf0 = (__half*)(smem_raw + SM_W_BYTES);   // buf0: row0(512B)|row1(512B)
    __half* hbuf1 = hbuf0 + 2 * Hdim;                   // buf1
    float*  sdt   = (float*)(smem_raw + SM_W_BYTES + SM_H_BYTES);
    float*  sx0   = sdt + Tdim;
    float*  sx1   = sx0 + Tdim;
    float*  sm0   = sx1 + Tdim;
    float*  sm1   = sm0 + Tdim;

    const int t    = threadIdx.x;
    const int j    = t >> 1;
    const int p    = t & 1;                  // row index AND k-half
    const int row0 = blockIdx.x * RPB;

    // cooperative copy: smem W slab = gg 0..8 (both p)
    {
        const float4* s1 = (const float4*)g_Wp;
        float4*       d1 = (float4*)sWp;
        for (int i = t; i < SM_W_BYTES / 16; i += THR) d1[i] = s1[i];
    }
    if (t < Tdim) {
        const float t1v = batch[t * 2];
        const float t0v = (t == 0) ? 0.f : batch[(t - 1) * 2];
        sdt[t] = t1v - t0v;
        sx0[t] = batch[((row0    ) * Tdim + t) * 2 + 1];
        sx1[t] = batch[((row0 + 1) * Tdim + t) * 2 + 1];
        sm0[t] = mask[(row0    ) * Tdim + t];
        sm1[t] = mask[(row0 + 1) * Tdim + t];
    }

    // this thread's M half-column -> 64 half2 registers
    __half2 mreg[KPH];
#pragma unroll
    for (int i = 0; i < KPH; i++) mreg[i] = g_Mh[(p * KPH + i) * Hdim + j];

    const float cj   = g_c[j];
    const float wih0 = W_ih[j], wih1 = W_ih[Hdim + j], wih2 = W_ih[2 * Hdim + j];
    const float bih0 = b_ih[j], bih1 = b_ih[Hdim + j], bih2 = b_ih[2 * Hdim + j];
    const float bhh0 = b_hh[j], bhh1 = b_hh[Hdim + j], bhh2 = b_hh[2 * Hdim + j];

    const float* sxk = p ? sx1 : sx0;
    const float* smk = p ? sm1 : sm0;

    // h-buffer byte offset for this thread's write (row p, lane j):
    // row array is p-interleaved float4s: slot(2q + half), q=(j&127)>>3, half=j>>7
    const int wslot  = 2 * ((j & 127) >> 3) + (j >> 7);
    const int woff   = p * 512 + wslot * 16 + (j & 7) * 2;   // bytes within buf

    __syncthreads();

    float hbr = 0.f;
    int pb = 0;

#pragma unroll 1
    for (int tt = 0; tt < Tdim; tt++) {
        const float dt = sdt[tt];
        const float xv = sxk[tt];
        const float mv = smk[tt];
        const float m0 = sm0[tt];
        const float m1 = sm1[tt];

        // ---- RK4: 4 stages ----
        float kprev = 0.f, acc = 0.f;
#pragma unroll 1
        for (int s = 0; s < 4; s++) {
            const float in = fmaf(Ccoef[s] * dt, kprev, hbr);
            __half* buf = pb ? hbuf1 : hbuf0;
            *(__half*)((char*)buf + woff) = __float2half_rn(in);
            __syncthreads();

            // partial dot over k-half p, both rows; paired accumulators
            // (chains of 32) merged with HADD2 -> single fp32 flush.
            const float4* b0 = (const float4*)buf;            // row0, 32 slots
            const float4* b1 = (const float4*)(buf + Hdim);   // row1
            const __half2 z2h = __floats2half2_rn(0.f, 0.f);
            __half2 sA0 = z2h, sA1 = z2h, sB0 = z2h, sB1 = z2h;
#pragma unroll
            for (int q = 0; q < 8; q++) {        // first 32 kp -> set A
                float4 v0 = b0[2 * q + p];
                float4 v1 = b1[2 * q + p];
                const __half2* pp0 = (const __half2*)&v0;
                const __half2* pp1 = (const __half2*)&v1;
#pragma unroll
                for (int u = 0; u < 4; u++) {
                    const __half2 m = mreg[q * 4 + u];
                    sA0 = __hfma2(m, pp0[u], sA0);
                    sA1 = __hfma2(m, pp1[u], sA1);
                }
            }
#pragma unroll
            for (int q = 8; q < 16; q++) {       // last 32 kp -> set B
                float4 v0 = b0[2 * q + p];
                float4 v1 = b1[2 * q + p];
                const __half2* pp0 = (const __half2*)&v0;
                const __half2* pp1 = (const __half2*)&v1;
#pragma unroll
                for (int u = 0; u < 4; u++) {
                    const __half2 m = mreg[q * 4 + u];
                    sB0 = __hfma2(m, pp0[u], sB0);
                    sB1 = __hfma2(m, pp1[u], sB1);
                }
            }
            const float2 f0 = __half22float2(__hadd2(sA0, sB0));
            const float2 f1 = __half22float2(__hadd2(sA1, sB1));
            const float pr0 = f0.x + f0.y;       // partial, row0
            const float pr1 = f1.x + f1.y;       // partial, row1
            const float psend = p ? pr0 : pr1;
            const float precv = __shfl_xor_sync(0xFFFFFFFFu, psend, 1);
            const float pmine = p ? pr1 : pr0;
            const float o = ftanh(cj + pmine + precv);
            acc = fmaf(Wcoef[s], o, acc);
            kprev = o;
            pb ^= 1;
        }

        const float hp = fmaf(dt, acc, hbr);

        // CTA-uniform GRU skip: when both rows are masked out, h_next = hp and
        // the whole GRU phase (incl. hp broadcast + bar) is dead work. Every
        // broadcast round rewrites the buffer fully, so parity stays safe.
        if (m0 == 0.f && m1 == 0.f) {
            hbr = hp;
            continue;
        }

        __half* buf = pb ? hbuf1 : hbuf0;
        *(__half*)((char*)buf + woff) = __float2half_rn(hp);
        __syncthreads();
        pb ^= 1;

        // ---- GRU partials: A = 9 smem groups, B = 7 streamed (pipelined) ----
        const float4* b0 = (const float4*)buf;
        const float4* b1 = (const float4*)(buf + Hdim);
        const __half2 z2h = __floats2half2_rn(0.f, 0.f);
        __half2 Ar0 = z2h, Ar1 = z2h, Az0 = z2h, Az1 = z2h, An0 = z2h, An1 = z2h;
        __half2 Br0 = z2h, Br1 = z2h, Bz0 = z2h, Bz1 = z2h, Bn0 = z2h, Bn1 = z2h;

        // depth-2 prefetch of streamed groups NGGS+0, NGGS+1
        uint4 pf[2][3];
#pragma unroll
        for (int s2 = 0; s2 < 2; s2++) {
            const int gg = NGGS + s2;
            pf[s2][0] = __ldg(&g_Wp[((gg * 3 + 0) * Hdim + j) * 2 + p]);
            pf[s2][1] = __ldg(&g_Wp[((gg * 3 + 1) * Hdim + j) * 2 + p]);
            pf[s2][2] = __ldg(&g_Wp[((gg * 3 + 2) * Hdim + j) * 2 + p]);
        }
#pragma unroll
        for (int i = 0; i < NGST; i++) {
            {   // smem group i -> A (covers in-flight LDG latency)
                uint4 u0 = sWp[((i * 3 + 0) * Hdim + j) * 2 + p];
                uint4 u1 = sWp[((i * 3 + 1) * Hdim + j) * 2 + p];
                uint4 u2 = sWp[((i * 3 + 2) * Hdim + j) * 2 + p];
                float4 hv0 = b0[2 * i + p];
                float4 hv1 = b1[2 * i + p];
                GRU_GROUP6(Ar0, Ar1, Az0, Az1, An0, An1, u0, u1, u2, hv0, hv1);
            }
            {   // streamed group NGGS+i from prefetch slot -> B, then refill
                const int gg = NGGS + i;
                uint4 u0 = pf[i & 1][0];
                uint4 u1 = pf[i & 1][1];
                uint4 u2 = pf[i & 1][2];
                if (i + 2 < NGST) {
                    const int gn = NGGS + i + 2;
                    pf[i & 1][0] = __ldg(&g_Wp[((gn * 3 + 0) * Hdim + j) * 2 + p]);
                    pf[i & 1][1] = __ldg(&g_Wp[((gn * 3 + 1) * Hdim + j) * 2 + p]);
                    pf[i & 1][2] = __ldg(&g_Wp[((gn * 3 + 2) * Hdim + j) * 2 + p]);
                }
                float4 hv0 = b0[2 * gg + p];
                float4 hv1 = b1[2 * gg + p];
                GRU_GROUP6(Br0, Br1, Bz0, Bz1, Bn0, Bn1, u0, u1, u2, hv0, hv1);
            }
        }
#pragma unroll
        for (int i = NGST; i < NGGS; i++) {     // smem groups 7, 8 -> A
            uint4 u0 = sWp[((i * 3 + 0) * Hdim + j) * 2 + p];
            uint4 u1 = sWp[((i * 3 + 1) * Hdim + j) * 2 + p];
            uint4 u2 = sWp[((i * 3 + 2) * Hdim + j) * 2 + p];
            float4 hv0 = b0[2 * i + p];
            float4 hv1 = b1[2 * i + p];
            GRU_GROUP6(Ar0, Ar1, Az0, Az1, An0, An1, u0, u1, u2, hv0, hv1);
        }

        const float2 fr0 = __half22float2(__hadd2(Ar0, Br0));
        const float2 fr1 = __half22float2(__hadd2(Ar1, Br1));
        const float2 fz0 = __half22float2(__hadd2(Az0, Bz0));
        const float2 fz1 = __half22float2(__hadd2(Az1, Bz1));
        const float2 fn0 = __half22float2(__hadd2(An0, Bn0));
        const float2 fn1 = __half22float2(__hadd2(An1, Bn1));
        const float r0s = fr0.x + fr0.y, r1s = fr1.x + fr1.y;
        const float z0s = fz0.x + fz0.y, z1s = fz1.x + fz1.y;
        const float n0s = fn0.x + fn0.y, n1s = fn1.x + fn1.y;

        // pairwise gate exchange via shfl (row p kept)
        const float grF = bhh0 + (p ? r1s : r0s)
                        + __shfl_xor_sync(0xFFFFFFFFu, p ? r0s : r1s, 1);
        const float gzF = bhh1 + (p ? z1s : z0s)
                        + __shfl_xor_sync(0xFFFFFFFFu, p ? z0s : z1s, 1);
        const float gnF = bhh2 + (p ? n1s : n0s)
                        + __shfl_xor_sync(0xFFFFFFFFu, p ? n0s : n1s, 1);

        // gates + mask blend (row p): all activations via MUFU tanh
        {
            const float r  = 0.5f * ftanh(0.5f * (fmaf(xv, wih0, bih0) + grF)) + 0.5f;
            const float zg = 0.5f * ftanh(0.5f * (fmaf(xv, wih1, bih1) + gzF)) + 0.5f;
            const float n  = ftanh(fmaf(xv, wih2, bih2) + r * gnF);
            const float ht = (1.f - zg) * n + zg * hp;
            hbr = mv * ht + (1.f - mv) * hp;
        }
    }

    out[(row0 + p) * Hdim + j] = hbr;
}

// ---------------------------------------------------------------------------
extern "C" void kernel_launch(void* const* d_in, const int* in_sizes, int n_in,
                              void* d_out, int out_size) {
    const float* batch = (const float*)d_in[0];
    const float* mask  = (const float*)d_in[1];
    const float* W1    = (const float*)d_in[2];
    const float* b1    = (const float*)d_in[3];
    const float* W2    = (const float*)d_in[4];
    const float* b2    = (const float*)d_in[5];
    const float* W_ih  = (const float*)d_in[6];
    const float* b_ih  = (const float*)d_in[7];
    const float* W_hh  = (const float*)d_in[8];
    const float* b_hh  = (const float*)d_in[9];

    cudaFuncSetAttribute(rnn_kernel, cudaFuncAttributeMaxDynamicSharedMemorySize,
                         SMEM_BYTES);

    prep_M1<<<dim3(64, 8), Hdim>>>(W1, W2);
    prep_Wg<<<Hdim, KP>>>(W_hh);
    prep_M2<<<Hdim, Hdim>>>(W2, b1, b2);
    rnn_kernel<<<NBLK, THR, SMEM_BYTES>>>(batch, mask, W_ih, b_ih, b_hh,
                                          (float*)d_out);
}

// round 17
// speedup vs baseline: 1.1918x; 1.0379x over previous
#include <cuda_runtime.h>
#include <cuda_fp16.h>

#define Hdim 256
#define Ddim 512
#define Bdim 256
#define Tdim 64
#define RPB  2
#define NBLK (Bdim / RPB)      // 128 CTAs -> 128 SMs busy
#define THR  512               // lane pairs: j = t>>1 (256), p = t&1 (row & k-half)
#define KP   (Hdim / 2)        // 128 k-pairs total
#define KPH  (KP / 2)          // 64 k-pairs per thread
#define NGG  16                // GRU gg-groups (each gg has p=0 and p=1 group)
#define NGGS 9                 // gg-groups resident in smem (216 KB)
#define NGST (NGG - NGGS)      // 7 streamed groups

#define SM_W_BYTES (NGGS * 3 * Hdim * 2 * 16)   // 221184
#define SM_H_BYTES (2 * 2 * Hdim * 2)           // 2 bufs x 2 rows x 256 half
#define SM_T_BYTES (5 * Tdim * 4)
#define SMEM_BYTES (SM_W_BYTES + SM_H_BYTES + SM_T_BYTES)

// g_Mh[kp*256 + j] = (M[2kp][j], M[2kp+1][j])
// g_Wp: p-interleaved GRU weights: uint4 index ((gg*3 + i)*Hdim + j)*2 + p.
// Word order in the 3 uint4 of a (gg,p,j) triple:
//   r0 z0 n0 r1 | z1 n1 r2 z2 | n2 r3 z3 n3.
__device__ __half2 g_Mh[KP * Hdim];
__device__ float   g_c[Hdim];
__device__ uint4   g_Wp[NGG * 3 * Hdim * 2];
__device__ float   g_Macc[8][Hdim][Hdim];   // prep scratch (2 MB)

__device__ __forceinline__ float ftanh(float x) {
    float y;
    asm("tanh.approx.f32 %0, %1;" : "=f"(y) : "f"(x));
    return y;
}
__device__ __forceinline__ __half2 u2h2(unsigned u) {
    return *reinterpret_cast<__half2*>(&u);
}

// ---------------------------------------------------------------------------
// prep_M1 / prep_M2 / prep_Wg: unchanged.
// ---------------------------------------------------------------------------
__global__ void prep_M1(const float* __restrict__ W1, const float* __restrict__ W2) {
    const int j0 = blockIdx.x * 4;
    const int c0 = blockIdx.y * 64;
    const int k  = threadIdx.x;
    __shared__ float w2s[4 * 64];
    w2s[k] = W2[(j0 + (k >> 6)) * Ddim + c0 + (k & 63)];
    __syncthreads();
    float a0 = 0.f, a1 = 0.f, a2 = 0.f, a3 = 0.f;
#pragma unroll 8
    for (int dd = 0; dd < 64; dd++) {
        const float w1v = W1[(c0 + dd) * Hdim + k];
        a0 = fmaf(w1v, w2s[0 * 64 + dd], a0);
        a1 = fmaf(w1v, w2s[1 * 64 + dd], a1);
        a2 = fmaf(w1v, w2s[2 * 64 + dd], a2);
        a3 = fmaf(w1v, w2s[3 * 64 + dd], a3);
    }
    g_Macc[blockIdx.y][j0 + 0][k] = a0;
    g_Macc[blockIdx.y][j0 + 1][k] = a1;
    g_Macc[blockIdx.y][j0 + 2][k] = a2;
    g_Macc[blockIdx.y][j0 + 3][k] = a3;
}

__global__ void prep_M2(const float* __restrict__ W2, const float* __restrict__ b1,
                        const float* __restrict__ b2) {
    const int j = blockIdx.x;
    const int k = threadIdx.x;
    float m = 0.f;
#pragma unroll
    for (int c = 0; c < 8; c++) m += g_Macc[c][j][k];
    __half* Mh = (__half*)g_Mh;
    Mh[(k >> 1) * (Hdim * 2) + j * 2 + (k & 1)] = __float2half_rn(m);

    __shared__ float red[Hdim];
    red[k] = W2[j * Ddim + k] * b1[k] + W2[j * Ddim + Hdim + k] * b1[Hdim + k];
    __syncthreads();
    for (int s = 128; s > 0; s >>= 1) {
        if (k < s) red[k] += red[k + s];
        __syncthreads();
    }
    if (k == 0) g_c[j] = red[0] + b2[j];
}

__global__ void prep_Wg(const float* __restrict__ W_hh) {
    const int j  = blockIdx.x;
    const int kp = threadIdx.x;
    const int g  = kp >> 2;
    const int q4 = kp & 3;
    const int p  = g >> 4;
    const int gg = g & 15;
    const int k0 = 2 * kp, k1 = 2 * kp + 1;
    float r0 = W_hh[(0 * Hdim + j) * Hdim + k0], r1 = W_hh[(0 * Hdim + j) * Hdim + k1];
    float z0 = W_hh[(1 * Hdim + j) * Hdim + k0], z1 = W_hh[(1 * Hdim + j) * Hdim + k1];
    float n0 = W_hh[(2 * Hdim + j) * Hdim + k0], n1 = W_hh[(2 * Hdim + j) * Hdim + k1];
    __half2 hr = __floats2half2_rn(r0, r1);
    __half2 hz = __floats2half2_rn(z0, z1);
    __half2 hn = __floats2half2_rn(n0, n1);
    unsigned* W = (unsigned*)g_Wp;
    const int s0 = 3 * q4;
#pragma unroll
    for (int c = 0; c < 3; c++) {
        const int s = s0 + c;
        unsigned v = (c == 0) ? *reinterpret_cast<unsigned*>(&hr)
                   : (c == 1) ? *reinterpret_cast<unsigned*>(&hz)
                              : *reinterpret_cast<unsigned*>(&hn);
        W[((((gg * 3 + (s >> 2)) * Hdim + j) * 2) + p) * 4 + (s & 3)] = v;
    }
}

// process one GRU 4-kp group into six named fp16 gate accumulators
#define GRU_GROUP6(cr0, cr1, cz0, cz1, cn0, cn1, u0, u1, u2, hv0, hv1)          \
    do {                                                                        \
        const __half2* p0 = (const __half2*)&hv0;                               \
        const __half2* p1 = (const __half2*)&hv1;                               \
        const __half2 wr0 = u2h2(u0.x), wz0 = u2h2(u0.y), wn0 = u2h2(u0.z);     \
        const __half2 wr1 = u2h2(u0.w), wz1 = u2h2(u1.x), wn1 = u2h2(u1.y);     \
        const __half2 wr2 = u2h2(u1.z), wz2 = u2h2(u1.w), wn2 = u2h2(u2.x);     \
        const __half2 wr3 = u2h2(u2.y), wz3 = u2h2(u2.z), wn3 = u2h2(u2.w);     \
        cr0 = __hfma2(wr0, p0[0], cr0); cr1 = __hfma2(wr0, p1[0], cr1);         \
        cz0 = __hfma2(wz0, p0[0], cz0); cz1 = __hfma2(wz0, p1[0], cz1);         \
        cn0 = __hfma2(wn0, p0[0], cn0); cn1 = __hfma2(wn0, p1[0], cn1);         \
        cr0 = __hfma2(wr1, p0[1], cr0); cr1 = __hfma2(wr1, p1[1], cr1);         \
        cz0 = __hfma2(wz1, p0[1], cz0); cz1 = __hfma2(wz1, p1[1], cz1);         \
        cn0 = __hfma2(wn1, p0[1], cn0); cn1 = __hfma2(wn1, p1[1], cn1);         \
        cr0 = __hfma2(wr2, p0[2], cr0); cr1 = __hfma2(wr2, p1[2], cr1);         \
        cz0 = __hfma2(wz2, p0[2], cz0); cz1 = __hfma2(wz2, p1[2], cz1);         \
        cn0 = __hfma2(wn2, p0[2], cn0); cn1 = __hfma2(wn2, p1[2], cn1);         \
        cr0 = __hfma2(wr3, p0[3], cr0); cr1 = __hfma2(wr3, p1[3], cr1);         \
        cz0 = __hfma2(wz3, p0[3], cz0); cz1 = __hfma2(wz3, p1[3], cz1);         \
        cn0 = __hfma2(wn3, p0[3], cn0); cn1 = __hfma2(wn3, p1[3], cn1);         \
    } while (0)

// ---------------------------------------------------------------------------
// ODE half-dot over this thread's 64 k-pairs, both rows; fp16 A/B chains of
// 32 kp merged with HADD2 -> single fp32 flush. Returns pr0/pr1.
// ---------------------------------------------------------------------------
__device__ __forceinline__ void ode_partial(const __half* __restrict__ buf, int p,
                                            const __half2 (&mreg)[KPH],
                                            float& pr0, float& pr1) {
    const float4* b0 = (const float4*)buf;            // row0, 32 slots
    const float4* b1 = (const float4*)(buf + Hdim);   // row1
    const __half2 z2h = __floats2half2_rn(0.f, 0.f);
    __half2 sA0 = z2h, sA1 = z2h, sB0 = z2h, sB1 = z2h;
#pragma unroll
    for (int q = 0; q < 8; q++) {        // first 32 kp -> set A
        float4 v0 = b0[2 * q + p];
        float4 v1 = b1[2 * q + p];
        const __half2* pp0 = (const __half2*)&v0;
        const __half2* pp1 = (const __half2*)&v1;
#pragma unroll
        for (int u = 0; u < 4; u++) {
            const __half2 m = mreg[q * 4 + u];
            sA0 = __hfma2(m, pp0[u], sA0);
            sA1 = __hfma2(m, pp1[u], sA1);
        }
    }
#pragma unroll
    for (int q = 8; q < 16; q++) {       // last 32 kp -> set B
        float4 v0 = b0[2 * q + p];
        float4 v1 = b1[2 * q + p];
        const __half2* pp0 = (const __half2*)&v0;
        const __half2* pp1 = (const __half2*)&v1;
#pragma unroll
        for (int u = 0; u < 4; u++) {
            const __half2 m = mreg[q * 4 + u];
            sB0 = __hfma2(m, pp0[u], sB0);
            sB1 = __hfma2(m, pp1[u], sB1);
        }
    }
    const float2 f0 = __half22float2(__hadd2(sA0, sB0));
    const float2 f1 = __half22float2(__hadd2(sA1, sB1));
    pr0 = f0.x + f0.y;
    pr1 = f1.x + f1.y;
}

// stage tail: pair exchange + tanh
__device__ __forceinline__ float stage_out(float pr0, float pr1, int p, float cj) {
    const float psend = p ? pr0 : pr1;
    const float precv = __shfl_xor_sync(0xFFFFFFFFu, psend, 1);
    const float pmine = p ? pr1 : pr0;
    return ftanh(cj + pmine + precv);
}

// ---------------------------------------------------------------------------
// Main recurrent kernel: R15 structure with the RK stage loop fully unrolled
// (literal coefficients, static ba/bb buffer pointers per step).
// Buffer schedule per step: ba, bb, ba, bb, ba(hp). Normal path flips step
// parity (5 writes); skip path (4 writes) preserves it. Every STS/LDS pair on
// a buffer is separated by >=1 intervening bar (verified stage-by-stage).
// ---------------------------------------------------------------------------
__global__ void __launch_bounds__(THR, 1) rnn_kernel(
    const float* __restrict__ batch, const float* __restrict__ mask,
    const float* __restrict__ W_ih, const float* __restrict__ b_ih,
    const float* __restrict__ b_hh, float* __restrict__ out) {

    extern __shared__ __align__(16) unsigned char smem_raw[];
    uint4*  sWp   = (uint4*)smem_raw;
    __half* hbuf0 = (__half*)(smem_raw + SM_W_BYTES);   // buf0: row0(512B)|row1(512B)
    __half* hbuf1 = hbuf0 + 2 * Hdim;                   // buf1
    float*  sdt   = (float*)(smem_raw + SM_W_BYTES + SM_H_BYTES);
    float*  sx0   = sdt + Tdim;
    float*  sx1   = sx0 + Tdim;
    float*  sm0   = sx1 + Tdim;
    float*  sm1   = sm0 + Tdim;

    const int t    = threadIdx.x;
    const int j    = t >> 1;
    const int p    = t & 1;                  // row index AND k-half
    const int row0 = blockIdx.x * RPB;

    // cooperative copy: smem W slab = gg 0..8 (both p)
    {
        const float4* s1 = (const float4*)g_Wp;
        float4*       d1 = (float4*)sWp;
        for (int i = t; i < SM_W_BYTES / 16; i += THR) d1[i] = s1[i];
    }
    if (t < Tdim) {
        const float t1v = batch[t * 2];
        const float t0v = (t == 0) ? 0.f : batch[(t - 1) * 2];
        sdt[t] = t1v - t0v;
        sx0[t] = batch[((row0    ) * Tdim + t) * 2 + 1];
        sx1[t] = batch[((row0 + 1) * Tdim + t) * 2 + 1];
        sm0[t] = mask[(row0    ) * Tdim + t];
        sm1[t] = mask[(row0 + 1) * Tdim + t];
    }

    // this thread's M half-column -> 64 half2 registers
    __half2 mreg[KPH];
#pragma unroll
    for (int i = 0; i < KPH; i++) mreg[i] = g_Mh[(p * KPH + i) * Hdim + j];

    const float cj   = g_c[j];
    const float wih0 = W_ih[j], wih1 = W_ih[Hdim + j], wih2 = W_ih[2 * Hdim + j];
    const float bih0 = b_ih[j], bih1 = b_ih[Hdim + j], bih2 = b_ih[2 * Hdim + j];
    const float bhh0 = b_hh[j], bhh1 = b_hh[Hdim + j], bhh2 = b_hh[2 * Hdim + j];

    const float* sxk = p ? sx1 : sx0;
    const float* smk = p ? sm1 : sm0;

    // h-buffer byte offset for this thread's write (row p, lane j):
    // row array is p-interleaved float4s: slot(2q + half), q=(j&127)>>3, half=j>>7
    const int wslot  = 2 * ((j & 127) >> 3) + (j >> 7);
    const int woff   = p * 512 + wslot * 16 + (j & 7) * 2;   // bytes within buf

    __syncthreads();

    float hbr = 0.f;
    int pb = 0;

#pragma unroll 1
    for (int tt = 0; tt < Tdim; tt++) {
        const float dt = sdt[tt];
        const float xv = sxk[tt];
        const float mv = smk[tt];
        const float m0 = sm0[tt];
        const float m1 = sm1[tt];

        __half* ba = pb ? hbuf1 : hbuf0;     // static per-step buffer roles
        __half* bb = pb ? hbuf0 : hbuf1;

        float pr0, pr1;

        // ---- RK4, fully unrolled ----
        // stage 1: input = hbr
        *(__half*)((char*)ba + woff) = __float2half_rn(hbr);
        __syncthreads();
        ode_partial(ba, p, mreg, pr0, pr1);
        const float o1 = stage_out(pr0, pr1, p, cj);

        // stage 2: input = hbr + 0.5 dt o1
        *(__half*)((char*)bb + woff) = __float2half_rn(fmaf(0.5f * dt, o1, hbr));
        __syncthreads();
        ode_partial(bb, p, mreg, pr0, pr1);
        const float o2 = stage_out(pr0, pr1, p, cj);

        // stage 3: input = hbr + 0.5 dt o2
        *(__half*)((char*)ba + woff) = __float2half_rn(fmaf(0.5f * dt, o2, hbr));
        __syncthreads();
        ode_partial(ba, p, mreg, pr0, pr1);
        const float o3 = stage_out(pr0, pr1, p, cj);

        // stage 4: input = hbr + dt o3
        *(__half*)((char*)bb + woff) = __float2half_rn(fmaf(dt, o3, hbr));
        __syncthreads();
        ode_partial(bb, p, mreg, pr0, pr1);
        const float o4 = stage_out(pr0, pr1, p, cj);

        // quadrature (same accumulation order as R15: w1 o1 + w2 o2 + ...)
        float acc = (1.f / 6.f) * o1;
        acc = fmaf(1.f / 3.f, o2, acc);
        acc = fmaf(1.f / 3.f, o3, acc);
        acc = fmaf(1.f / 6.f, o4, acc);
        const float hp = fmaf(dt, acc, hbr);

        // CTA-uniform GRU skip: both rows masked out -> h_next = hp.
        // 4 writes this step -> parity preserved (pb unchanged).
        if (m0 == 0.f && m1 == 0.f) {
            hbr = hp;
            continue;
        }

        // hp broadcast (5th write -> step parity flips)
        *(__half*)((char*)ba + woff) = __float2half_rn(hp);
        __syncthreads();
        pb ^= 1;

        // ---- GRU partials: A = 9 smem groups, B = 7 streamed (pipelined) ----
        const float4* b0 = (const float4*)ba;
        const float4* b1 = (const float4*)(ba + Hdim);
        const __half2 z2h = __floats2half2_rn(0.f, 0.f);
        __half2 Ar0 = z2h, Ar1 = z2h, Az0 = z2h, Az1 = z2h, An0 = z2h, An1 = z2h;
        __half2 Br0 = z2h, Br1 = z2h, Bz0 = z2h, Bz1 = z2h, Bn0 = z2h, Bn1 = z2h;

        // depth-2 prefetch of streamed groups NGGS+0, NGGS+1
        uint4 pf[2][3];
#pragma unroll
        for (int s2 = 0; s2 < 2; s2++) {
            const int gg = NGGS + s2;
            pf[s2][0] = __ldg(&g_Wp[((gg * 3 + 0) * Hdim + j) * 2 + p]);
            pf[s2][1] = __ldg(&g_Wp[((gg * 3 + 1) * Hdim + j) * 2 + p]);
            pf[s2][2] = __ldg(&g_Wp[((gg * 3 + 2) * Hdim + j) * 2 + p]);
        }
#pragma unroll
        for (int i = 0; i < NGST; i++) {
            {   // smem group i -> A (covers in-flight LDG latency)
                uint4 u0 = sWp[((i * 3 + 0) * Hdim + j) * 2 + p];
                uint4 u1 = sWp[((i * 3 + 1) * Hdim + j) * 2 + p];
                uint4 u2 = sWp[((i * 3 + 2) * Hdim + j) * 2 + p];
                float4 hv0 = b0[2 * i + p];
                float4 hv1 = b1[2 * i + p];
                GRU_GROUP6(Ar0, Ar1, Az0, Az1, An0, An1, u0, u1, u2, hv0, hv1);
            }
            {   // streamed group NGGS+i from prefetch slot -> B, then refill
                const int gg = NGGS + i;
                uint4 u0 = pf[i & 1][0];
                uint4 u1 = pf[i & 1][1];
                uint4 u2 = pf[i & 1][2];
                if (i + 2 < NGST) {
                    const int gn = NGGS + i + 2;
                    pf[i & 1][0] = __ldg(&g_Wp[((gn * 3 + 0) * Hdim + j) * 2 + p]);
                    pf[i & 1][1] = __ldg(&g_Wp[((gn * 3 + 1) * Hdim + j) * 2 + p]);
                    pf[i & 1][2] = __ldg(&g_Wp[((gn * 3 + 2) * Hdim + j) * 2 + p]);
                }
                float4 hv0 = b0[2 * gg + p];
                float4 hv1 = b1[2 * gg + p];
                GRU_GROUP6(Br0, Br1, Bz0, Bz1, Bn0, Bn1, u0, u1, u2, hv0, hv1);
            }
        }
#pragma unroll
        for (int i = NGST; i < NGGS; i++) {     // smem groups 7, 8 -> A
            uint4 u0 = sWp[((i * 3 + 0) * Hdim + j) * 2 + p];
            uint4 u1 = sWp[((i * 3 + 1) * Hdim + j) * 2 + p];
            uint4 u2 = sWp[((i * 3 + 2) * Hdim + j) * 2 + p];
            float4 hv0 = b0[2 * i + p];
            float4 hv1 = b1[2 * i + p];
            GRU_GROUP6(Ar0, Ar1, Az0, Az1, An0, An1, u0, u1, u2, hv0, hv1);
        }

        const float2 fr0 = __half22float2(__hadd2(Ar0, Br0));
        const float2 fr1 = __half22float2(__hadd2(Ar1, Br1));
        const float2 fz0 = __half22float2(__hadd2(Az0, Bz0));
        const float2 fz1 = __half22float2(__hadd2(Az1, Bz1));
        const float2 fn0 = __half22float2(__hadd2(An0, Bn0));
        const float2 fn1 = __half22float2(__hadd2(An1, Bn1));
        const float r0s = fr0.x + fr0.y, r1s = fr1.x + fr1.y;
        const float z0s = fz0.x + fz0.y, z1s = fz1.x + fz1.y;
        const float n0s = fn0.x + fn0.y, n1s = fn1.x + fn1.y;

        // pairwise gate exchange via shfl (row p kept)
        const float grF = bhh0 + (p ? r1s : r0s)
                        + __shfl_xor_sync(0xFFFFFFFFu, p ? r0s : r1s, 1);
        const float gzF = bhh1 + (p ? z1s : z0s)
                        + __shfl_xor_sync(0xFFFFFFFFu, p ? z0s : z1s, 1);
        const float gnF = bhh2 + (p ? n1s : n0s)
                        + __shfl_xor_sync(0xFFFFFFFFu, p ? n0s : n1s, 1);

        // gates + mask blend (row p): all activations via MUFU tanh
        {
            const float r  = 0.5f * ftanh(0.5f * (fmaf(xv, wih0, bih0) + grF)) + 0.5f;
            const float zg = 0.5f * ftanh(0.5f * (fmaf(xv, wih1, bih1) + gzF)) + 0.5f;
            const float n  = ftanh(fmaf(xv, wih2, bih2) + r * gnF);
            const float ht = (1.f - zg) * n + zg * hp;
            hbr = mv * ht + (1.f - mv) * hp;
        }
    }

    out[(row0 + p) * Hdim + j] = hbr;
}

// ---------------------------------------------------------------------------
extern "C" void kernel_launch(void* const* d_in, const int* in_sizes, int n_in,
                              void* d_out, int out_size) {
    const float* batch = (const float*)d_in[0];
    const float* mask  = (const float*)d_in[1];
    const float* W1    = (const float*)d_in[2];
    const float* b1    = (const float*)d_in[3];
    const float* W2    = (const float*)d_in[4];
    const float* b2    = (const float*)d_in[5];
    const float* W_ih  = (const float*)d_in[6];
    const float* b_ih  = (const float*)d_in[7];
    const float* W_hh  = (const float*)d_in[8];
    const float* b_hh  = (const float*)d_in[9];

    cudaFuncSetAttribute(rnn_kernel, cudaFuncAttributeMaxDynamicSharedMemorySize,
                         SMEM_BYTES);

    prep_M1<<<dim3(64, 8), Hdim>>>(W1, W2);
    prep_Wg<<<Hdim, KP>>>(W_hh);
    prep_M2<<<Hdim, Hdim>>>(W2, b1, b2);
    rnn_kernel<<<NBLK, THR, SMEM_BYTES>>>(batch, mask, W_ih, b_ih, b_hh,
                                          (float*)d_out);
}